// round 13
// baseline (speedup 1.0000x reference)
#include <cuda_runtime.h>
#include <cuda_bf16.h>
#include <cuda_fp16.h>
#include <cstdint>

#define NB  2
#define CC  512
#define THW 6272
#define CT  (CC*THW)
#define EEL ((size_t)THW*(size_t)THW)
#define K3  (3*CC)                         // 1536

// ---------------- device scratch ----------------
__device__ float g_wz[NB*CT];                        // fp32 Wz projection [c,t]
__device__ float g_me[NB*CT];                        // mask_energy fp32
__device__ __half g_att [NB*EEL];                    // energy -> attention fp16 [t,s]
__device__ __nv_bfloat16 g_x3 [NB*(size_t)THW*K3];  // [t, x_hi|x_lo|x_hi] bf16 (wz branch)
__device__ __nv_bfloat16 g_Wz3[CC*K3];               // [o, hi|hi|lo] bf16
__device__ __half g_xh  [NB*CT];                     // x^T [t,c] fp16
__device__ __half g_maskT[NB*CT];                    // mask^T [s,c] fp16
__device__ __half g_whgm[3*CC*CC];                   // Wh,Wg,Wm fp16 [o,c]
__device__ __half g_wT  [2*CC*CC];                   // WhT,WgT fp16 [c,o]
__device__ __half g_MT  [CC*CC];                     // (Wh^T Wg)^T fp16 [k,c]
__device__ __half g_xM  [NB*CT];                     // x^T(Wh^T Wg) fp16 [t,k]
__device__ __half g_phm [NB*CT];                     // [c,s] fp16
__device__ __half g_pm  [NB*CT];                     // [c,t] fp16
__device__ float g_vb  [CC];                         // Wg^T bh
__device__ float g_beta[NB*THW];                     // x^T (Wg^T bh)  [s]
__device__ float g_scale[CC];
__device__ float g_shift[CC];

// ---------------- helpers ----------------
__device__ __forceinline__ uint32_t smem_u32(const void* p) {
    uint32_t a;
    asm("{ .reg .u64 t; cvta.to.shared.u64 t, %1; cvt.u32.u64 %0, t; }" : "=r"(a) : "l"(p));
    return a;
}
#define SWZ128(o) ((o) ^ (((o) >> 3) & 0x70))
__device__ __forceinline__ void cp16(uint32_t s, const void* g) {
    asm volatile("cp.async.cg.shared.global [%0], [%1], 16;" :: "r"(s), "l"(g));
}
#define CP_COMMIT() asm volatile("cp.async.commit_group;" ::: "memory")
#define CP_WAIT(n)  asm volatile("cp.async.wait_group %0;" :: "n"(n) : "memory")

__device__ __forceinline__ void ldmx4(uint32_t& r0, uint32_t& r1, uint32_t& r2, uint32_t& r3,
                                      uint32_t addr) {
    asm volatile("ldmatrix.sync.aligned.m8n8.x4.shared.b16 {%0,%1,%2,%3}, [%4];"
                 : "=r"(r0), "=r"(r1), "=r"(r2), "=r"(r3) : "r"(addr));
}
__device__ __forceinline__ void mma_bf16(float* d, const uint32_t* a, const uint32_t* b) {
    asm volatile("mma.sync.aligned.m16n8k16.row.col.f32.bf16.bf16.f32 "
                 "{%0,%1,%2,%3}, {%4,%5,%6,%7}, {%8,%9}, {%0,%1,%2,%3};"
                 : "+f"(d[0]), "+f"(d[1]), "+f"(d[2]), "+f"(d[3])
                 : "r"(a[0]), "r"(a[1]), "r"(a[2]), "r"(a[3]), "r"(b[0]), "r"(b[1]));
}
__device__ __forceinline__ void mma_f16(uint32_t* d, const uint32_t* a, const uint32_t* b) {
    asm volatile("mma.sync.aligned.m16n8k16.row.col.f16.f16.f16.f16 "
                 "{%0,%1}, {%2,%3,%4,%5}, {%6,%7}, {%0,%1};"
                 : "+r"(d[0]), "+r"(d[1])
                 : "r"(a[0]), "r"(a[1]), "r"(a[2]), "r"(a[3]), "r"(b[0]), "r"(b[1]));
}

#define STAGES 3

// ================= fp16 HMMA TN GEMM (fp16 accumulate) =================
// C[m,n] = sum_k A[m,k]*B[n,k] (+bias_m[m]) (+bias_n[z*sBiasN + n]); out_kind: 0=f32, 1=f16
__global__ void __launch_bounds__(256)
gemm_f16_mma(const __half* __restrict__ A, const __half* __restrict__ B,
             void* __restrict__ Cv, int out_kind,
             const float* __restrict__ bias_m, const float* __restrict__ bias_n,
             int M, int N, int K, int ldA, int ldB,
             long long sA, long long sB, long long sC, long long sBiasN)
{
    extern __shared__ char smem[];
    const uint32_t sb = smem_u32(smem);
    const int tid = threadIdx.x, wid = tid >> 5, lane = tid & 31;
    const int wm = wid & 1, wn = wid >> 1;
    const int m_w = wm * 64, n_w = wn * 32;

    uint32_t bufA[STAGES], bufB[STAGES];
#pragma unroll
    for (int s = 0; s < STAGES; s++) { bufA[s] = sb + s * 32768; bufB[s] = bufA[s] + 16384; }

    const int m0 = blockIdx.y * 128, n0 = blockIdx.x * 128;
    const char* Ab = (const char*)(A + (long long)blockIdx.z * sA + (long long)m0 * ldA);
    const char* Bb = (const char*)(B + (long long)blockIdx.z * sB + (long long)n0 * ldB);
    const long long rbA = (long long)ldA * 2;
    const long long rbB = (long long)ldB * 2;
    const int nc = K >> 6;

    const int lrow = tid >> 3;
    const int lcol = (tid & 7) << 4;

    auto load_chunk = [&](int c, int s) {
        const char* ga = Ab + (long long)c * 128;
        const char* gb = Bb + (long long)c * 128;
#pragma unroll
        for (int i = 0; i < 4; i++) {
            int row = lrow + i * 32;
            uint32_t off = SWZ128((uint32_t)(row * 128 + lcol));
            long long go = (long long)row;
            cp16(bufA[s] + off, ga + go * rbA + lcol);
            cp16(bufB[s] + off, gb + go * rbB + lcol);
        }
    };

    uint32_t acc[4][4][2];
#pragma unroll
    for (int i = 0; i < 4; i++)
#pragma unroll
        for (int j = 0; j < 4; j++) { acc[i][j][0] = 0u; acc[i][j][1] = 0u; }

    const int grp = lane >> 3, rw = lane & 7;
    const int a_row = (grp & 1) * 8 + rw;
    const int a_kh  = (grp >> 1) * 16;
    const int b_row = (grp >> 1) * 8 + rw;
    const int b_kh  = (grp & 1) * 16;

    load_chunk(0, 0); CP_COMMIT();
    if (nc > 1) { load_chunk(1, 1); CP_COMMIT(); }

    for (int c = 0; c < nc; c++) {
        if (c + 1 < nc) { CP_WAIT(1); } else { CP_WAIT(0); }
        __syncthreads();
        if (c + 2 < nc) { load_chunk(c + 2, (c + 2) % STAGES); CP_COMMIT(); }
        const uint32_t sa = bufA[c % STAGES], sbm = bufB[c % STAGES];
#pragma unroll
        for (int kk = 0; kk < 4; kk++) {
            const int kb = kk * 32;
            uint32_t a[4][4], b[4][2];
#pragma unroll
            for (int mt = 0; mt < 4; mt++) {
                int row = m_w + mt * 16 + a_row;
                uint32_t ad = sa + SWZ128((uint32_t)(row * 128 + kb + a_kh));
                ldmx4(a[mt][0], a[mt][1], a[mt][2], a[mt][3], ad);
            }
#pragma unroll
            for (int np = 0; np < 2; np++) {
                int row = n_w + np * 16 + b_row;
                uint32_t bd = sbm + SWZ128((uint32_t)(row * 128 + kb + b_kh));
                uint32_t r0, r1, r2, r3;
                ldmx4(r0, r1, r2, r3, bd);
                b[np * 2][0] = r0; b[np * 2][1] = r1;
                b[np * 2 + 1][0] = r2; b[np * 2 + 1][1] = r3;
            }
#pragma unroll
            for (int mt = 0; mt < 4; mt++)
#pragma unroll
                for (int nt = 0; nt < 4; nt++)
                    mma_f16(acc[mt][nt], a[mt], b[nt]);
        }
    }

    const int r_lo = lane >> 2, c_off = (lane & 3) * 2;
    const float* bnz = bias_n ? (bias_n + (long long)blockIdx.z * sBiasN) : nullptr;
#pragma unroll
    for (int mt = 0; mt < 4; mt++) {
        int row = m0 + m_w + mt * 16 + r_lo;
#pragma unroll
        for (int half = 0; half < 2; half++) {
            int r = row + half * 8;
            float bmv = bias_m ? bias_m[r] : 0.f;
            long long base = (long long)blockIdx.z * sC + (long long)r * N + n0 + n_w + c_off;
#pragma unroll
            for (int nt = 0; nt < 4; nt++) {
                float2 v = __half22float2(*reinterpret_cast<__half2*>(&acc[mt][nt][half]));
                v.x += bmv; v.y += bmv;
                int col = n0 + n_w + nt * 8 + c_off;
                if (bnz) { v.x += bnz[col]; v.y += bnz[col + 1]; }
                if (out_kind == 1) {
                    *reinterpret_cast<__half2*>((__half*)Cv + base + nt * 8) =
                        __floats2half2_rn(v.x, v.y);
                } else {
                    *reinterpret_cast<float2*>((float*)Cv + base + nt * 8) = v;
                }
            }
        }
    }
}

// ================= bf16 HMMA TN GEMM (fp32 accumulate; wz branch) =================
__global__ void __launch_bounds__(256)
gemm_bf16_mma(const __nv_bfloat16* __restrict__ A, const __nv_bfloat16* __restrict__ B,
              float* __restrict__ Cv,
              const float* __restrict__ bias_m,
              int M, int N, int K, int ldA, int ldB,
              long long sA, long long sB, long long sC)
{
    extern __shared__ char smem[];
    const uint32_t sb = smem_u32(smem);
    const int tid = threadIdx.x, wid = tid >> 5, lane = tid & 31;
    const int wm = wid & 1, wn = wid >> 1;
    const int m_w = wm * 64, n_w = wn * 32;

    uint32_t bufA[STAGES], bufB[STAGES];
#pragma unroll
    for (int s = 0; s < STAGES; s++) { bufA[s] = sb + s * 32768; bufB[s] = bufA[s] + 16384; }

    const int m0 = blockIdx.y * 128, n0 = blockIdx.x * 128;
    const char* Ab = (const char*)(A + (long long)blockIdx.z * sA + (long long)m0 * ldA);
    const char* Bb = (const char*)(B + (long long)blockIdx.z * sB + (long long)n0 * ldB);
    const long long rbA = (long long)ldA * 2;
    const long long rbB = (long long)ldB * 2;
    const int nc = K >> 6;

    const int lrow = tid >> 3;
    const int lcol = (tid & 7) << 4;

    auto load_chunk = [&](int c, int s) {
        const char* ga = Ab + (long long)c * 128;
        const char* gb = Bb + (long long)c * 128;
#pragma unroll
        for (int i = 0; i < 4; i++) {
            int row = lrow + i * 32;
            uint32_t off = SWZ128((uint32_t)(row * 128 + lcol));
            long long go = (long long)row;
            cp16(bufA[s] + off, ga + go * rbA + lcol);
            cp16(bufB[s] + off, gb + go * rbB + lcol);
        }
    };

    float acc[4][4][4];
#pragma unroll
    for (int i = 0; i < 4; i++)
#pragma unroll
        for (int j = 0; j < 4; j++)
#pragma unroll
            for (int q = 0; q < 4; q++) acc[i][j][q] = 0.f;

    const int grp = lane >> 3, rw = lane & 7;
    const int a_row = (grp & 1) * 8 + rw;
    const int a_kh  = (grp >> 1) * 16;
    const int b_row = (grp >> 1) * 8 + rw;
    const int b_kh  = (grp & 1) * 16;

    load_chunk(0, 0); CP_COMMIT();
    if (nc > 1) { load_chunk(1, 1); CP_COMMIT(); }

    for (int c = 0; c < nc; c++) {
        if (c + 1 < nc) { CP_WAIT(1); } else { CP_WAIT(0); }
        __syncthreads();
        if (c + 2 < nc) { load_chunk(c + 2, (c + 2) % STAGES); CP_COMMIT(); }
        const uint32_t sa = bufA[c % STAGES], sbm = bufB[c % STAGES];
#pragma unroll
        for (int kk = 0; kk < 4; kk++) {
            const int kb = kk * 32;
            uint32_t a[4][4], b[4][2];
#pragma unroll
            for (int mt = 0; mt < 4; mt++) {
                int row = m_w + mt * 16 + a_row;
                uint32_t ad = sa + SWZ128((uint32_t)(row * 128 + kb + a_kh));
                ldmx4(a[mt][0], a[mt][1], a[mt][2], a[mt][3], ad);
            }
#pragma unroll
            for (int np = 0; np < 2; np++) {
                int row = n_w + np * 16 + b_row;
                uint32_t bd = sbm + SWZ128((uint32_t)(row * 128 + kb + b_kh));
                uint32_t r0, r1, r2, r3;
                ldmx4(r0, r1, r2, r3, bd);
                b[np * 2][0] = r0; b[np * 2][1] = r1;
                b[np * 2 + 1][0] = r2; b[np * 2 + 1][1] = r3;
            }
#pragma unroll
            for (int mt = 0; mt < 4; mt++)
#pragma unroll
                for (int nt = 0; nt < 4; nt++)
                    mma_bf16(acc[mt][nt], a[mt], b[nt]);
        }
    }

    const int r_lo = lane >> 2, c_off = (lane & 3) * 2;
#pragma unroll
    for (int mt = 0; mt < 4; mt++) {
        int row = m0 + m_w + mt * 16 + r_lo;
#pragma unroll
        for (int half = 0; half < 2; half++) {
            int r = row + half * 8;
            float bmv = bias_m ? bias_m[r] : 0.f;
            long long base = (long long)blockIdx.z * sC + (long long)r * N + n0 + n_w + c_off;
#pragma unroll
            for (int nt = 0; nt < 4; nt++) {
                float v0 = acc[mt][nt][half * 2 + 0] + bmv;
                float v1 = acc[mt][nt][half * 2 + 1] + bmv;
                *reinterpret_cast<float2*>(Cv + base + nt * 8) = make_float2(v0, v1);
            }
        }
    }
}

// ---------------- prep: Wh,Wg,Wm -> fp16 [o,c]; WhT,WgT fp16 [c,o]; vb = Wg^T bh ----------------
__global__ void prep_weights(const float* __restrict__ Wh, const float* __restrict__ Wg,
                             const float* __restrict__ Wm, const float* __restrict__ bh,
                             __half* __restrict__ whgm, __half* __restrict__ wT,
                             float* __restrict__ vb)
{
    int i = blockIdx.x * blockDim.x + threadIdx.x;
    int n = CC * CC;
    if (i < n) {
        int o = i / CC, c = i - o * CC;
        __half h = __float2half(Wh[i]);
        whgm[i] = h;
        wT[c * CC + o] = h;                    // WhT
    } else if (i < 2 * n) {
        int j = i - n;
        int o = j / CC, c = j - o * CC;
        __half h = __float2half(Wg[j]);
        whgm[i] = h;
        wT[n + c * CC + o] = h;                // WgT
    } else if (i < 3 * n) {
        whgm[i] = __float2half(Wm[i - 2 * n]);
    } else if (i < 3 * n + CC) {
        int c = i - 3 * n;
        float s = 0.f;
        for (int o = 0; o < CC; o++) s += Wg[o * CC + c] * bh[o];
        vb[c] = s;
    }
}

// ---------------- Wz [o,c] fp32 -> Wz3 [o, hi|hi|lo] bf16 ----------------
__global__ void split_w(const float* __restrict__ in, __nv_bfloat16* __restrict__ out)
{
    int i = blockIdx.x * blockDim.x + threadIdx.x;
    if (i >= CC * CC) return;
    int o = i / CC, c = i - o * CC;
    float v = in[i];
    __nv_bfloat16 hi = __float2bfloat16(v);
    __nv_bfloat16 lo = __float2bfloat16(v - __bfloat162float(hi));
    out[(long long)o * K3 + c]          = hi;
    out[(long long)o * K3 + CC + c]     = hi;
    out[(long long)o * K3 + 2 * CC + c] = lo;
}

// ---------------- x [c,t] fp32 -> x3 bf16 [t, hi|lo|hi] AND xh fp16 [t,c] ----------------
__global__ void split_x(const float* __restrict__ in, __nv_bfloat16* __restrict__ x3,
                        __half* __restrict__ xh, long long sIn, long long sX3, long long sXh)
{
    __shared__ float tile[32][33];
    const float* ib = in + (long long)blockIdx.z * sIn;
    __nv_bfloat16* o3 = x3 + (long long)blockIdx.z * sX3;
    __half* oh = xh + (long long)blockIdx.z * sXh;
    int t0 = blockIdx.x * 32, c0 = blockIdx.y * 32;
    int x = threadIdx.x, y = threadIdx.y;
#pragma unroll
    for (int i = 0; i < 32; i += 8)
        tile[y + i][x] = ib[(long long)(c0 + y + i) * THW + t0 + x];
    __syncthreads();
#pragma unroll
    for (int i = 0; i < 32; i += 8) {
        float v = tile[x][y + i];
        __nv_bfloat16 hi = __float2bfloat16(v);
        __nv_bfloat16 lo = __float2bfloat16(v - __bfloat162float(hi));
        long long row = (long long)(t0 + y + i) * K3;
        o3[row + c0 + x]          = hi;
        o3[row + CC + c0 + x]     = lo;
        o3[row + 2 * CC + c0 + x] = hi;
        oh[(long long)(t0 + y + i) * CC + c0 + x] = __float2half(v);
    }
}

// ---------------- transpose + fp32->fp16 (mask^T) ----------------
__global__ void transpose_cvt(const float* __restrict__ in, __half* __restrict__ out,
                              long long sIn, long long sOut)
{
    __shared__ float tile[32][33];
    const float* ib = in + (long long)blockIdx.z * sIn;
    __half* ob = out + (long long)blockIdx.z * sOut;
    int t0 = blockIdx.x * 32, c0 = blockIdx.y * 32;
    int x = threadIdx.x, y = threadIdx.y;
#pragma unroll
    for (int i = 0; i < 32; i += 8)
        tile[y + i][x] = ib[(long long)(c0 + y + i) * THW + t0 + x];
    __syncthreads();
#pragma unroll
    for (int i = 0; i < 32; i += 8)
        ob[(long long)(t0 + y + i) * CC + c0 + x] = __float2half(tile[x][y + i]);
}

// ---------------- beta[z][s] = sum_c xh[z][s,c] * vb[c]  (one warp per row) ----------------
__global__ void __launch_bounds__(256)
beta_k(const __half* __restrict__ xh, const float* __restrict__ vb,
       float* __restrict__ beta)
{
    int wrow = (blockIdx.x * blockDim.x + threadIdx.x) >> 5;   // global warp id
    int lane = threadIdx.x & 31;
    if (wrow >= NB * THW) return;
    const __half* p = xh + (long long)wrow * CC;
    float s = 0.f;
#pragma unroll
    for (int i = 0; i < 16; i++) {
        int c = lane + i * 32;
        s += __half2float(p[c]) * vb[c];
    }
#pragma unroll
    for (int o = 16; o; o >>= 1) s += __shfl_xor_sync(0xffffffffu, s, o);
    if (lane == 0) beta[wrow] = s;
}

// ---------------- softmax fp16 in-place (attention) ----------------
__global__ void __launch_bounds__(256)
softmax_h(__half* __restrict__ data, int rowlen)
{
    __half* p = data + (long long)blockIdx.x * rowlen;
    const int tid = threadIdx.x;
    __shared__ float red[8];

    float v[25];
    float mx = -3.0e38f;
#pragma unroll
    for (int i = 0; i < 25; i++) {
        int idx = tid + (i << 8);
        v[i] = (idx < rowlen) ? __half2float(p[idx]) : -3.0e38f;
        mx = fmaxf(mx, v[i]);
    }
#pragma unroll
    for (int o = 16; o; o >>= 1) mx = fmaxf(mx, __shfl_xor_sync(0xffffffffu, mx, o));
    if ((tid & 31) == 0) red[tid >> 5] = mx;
    __syncthreads();
    mx = red[0];
#pragma unroll
    for (int w = 1; w < 8; w++) mx = fmaxf(mx, red[w]);
    __syncthreads();

    float s = 0.f;
#pragma unroll
    for (int i = 0; i < 25; i++) { v[i] = __expf(v[i] - mx); s += v[i]; }
#pragma unroll
    for (int o = 16; o; o >>= 1) s += __shfl_xor_sync(0xffffffffu, s, o);
    if ((tid & 31) == 0) red[tid >> 5] = s;
    __syncthreads();
    s = 0.f;
#pragma unroll
    for (int w = 0; w < 8; w++) s += red[w];
    float inv = 1.f / s;
#pragma unroll
    for (int i = 0; i < 25; i++) {
        int idx = tid + (i << 8);
        if (idx < rowlen) p[idx] = __float2half(v[i] * inv);
    }
}

// ---------------- BN stats on g_wz ----------------
__global__ void __launch_bounds__(256)
bn_stats(const float* __restrict__ wz, const float* __restrict__ bn_w,
         const float* __restrict__ bn_b, float* __restrict__ scale,
         float* __restrict__ shift)
{
    int c = blockIdx.x;
    int tid = threadIdx.x;
    float s = 0.f, sq = 0.f;
    for (int i = tid; i < NB * THW; i += 256) {
        int n = i / THW, t = i - n * THW;
        float v = wz[(long long)n * CT + (long long)c * THW + t];
        s += v;
        sq = fmaf(v, v, sq);
    }
    __shared__ float r1[8], r2[8];
#pragma unroll
    for (int o = 16; o; o >>= 1) {
        s  += __shfl_xor_sync(0xffffffffu, s,  o);
        sq += __shfl_xor_sync(0xffffffffu, sq, o);
    }
    if ((tid & 31) == 0) { r1[tid >> 5] = s; r2[tid >> 5] = sq; }
    __syncthreads();
    if (tid == 0) {
        s = 0.f; sq = 0.f;
#pragma unroll
        for (int w = 0; w < 8; w++) { s += r1[w]; sq += r2[w]; }
        const float invn = 1.f / (float)(NB * THW);
        float mu  = s * invn;
        float var = sq * invn - mu * mu;
        float sc  = bn_w[c] * rsqrtf(var + 1e-5f);
        scale[c] = sc;
        shift[c] = bn_b[c] - mu * sc;
    }
}

// ---------------- fused: mask_atten = softmax_t(me); out = gamma*pm*mask_atten + BN(wz) ----------------
__global__ void __launch_bounds__(256)
softmax_final(const float* __restrict__ me, const __half* __restrict__ pm,
              const float* __restrict__ wz, const float* __restrict__ scale,
              const float* __restrict__ shift, const float* __restrict__ gamma,
              float* __restrict__ out)
{
    const int blk = blockIdx.x;
    const int c = blk % CC;
    const long long base = (long long)blk * THW;
    const float* p = me + base;
    const int tid = threadIdx.x;
    __shared__ float red[8];

    float v[25];
    float mx = -3.0e38f;
#pragma unroll
    for (int i = 0; i < 25; i++) {
        int idx = tid + (i << 8);
        v[i] = (idx < THW) ? p[idx] : -3.0e38f;
        mx = fmaxf(mx, v[i]);
    }
#pragma unroll
    for (int o = 16; o; o >>= 1) mx = fmaxf(mx, __shfl_xor_sync(0xffffffffu, mx, o));
    if ((tid & 31) == 0) red[tid >> 5] = mx;
    __syncthreads();
    mx = red[0];
#pragma unroll
    for (int w = 1; w < 8; w++) mx = fmaxf(mx, red[w]);
    __syncthreads();

    float s = 0.f;
#pragma unroll
    for (int i = 0; i < 25; i++) { v[i] = __expf(v[i] - mx); s += v[i]; }
#pragma unroll
    for (int o = 16; o; o >>= 1) s += __shfl_xor_sync(0xffffffffu, s, o);
    if ((tid & 31) == 0) red[tid >> 5] = s;
    __syncthreads();
    s = 0.f;
#pragma unroll
    for (int w = 0; w < 8; w++) s += red[w];

    const float inv = 1.f / s;
    const float g  = gamma[0];
    const float sc = scale[c], sh = shift[c];
#pragma unroll
    for (int i = 0; i < 25; i++) {
        int idx = tid + (i << 8);
        if (idx < THW) {
            float ma  = v[i] * inv;
            float pmv = __half2float(pm[base + idx]);
            out[base + idx] = g * pmv * ma + fmaf(wz[base + idx], sc, sh);
        }
    }
}

// ---------------- launch ----------------
extern "C" void kernel_launch(void* const* d_in, const int* in_sizes, int n_in,
                              void* d_out, int out_size)
{
    const float* x    = (const float*)d_in[0];
    const float* mask = (const float*)d_in[1];
    const float* Wh   = (const float*)d_in[2];
    const float* bh   = (const float*)d_in[3];
    const float* Wg   = (const float*)d_in[4];
    const float* bg   = (const float*)d_in[5];
    const float* Wm   = (const float*)d_in[6];
    const float* bm   = (const float*)d_in[7];
    const float* Wz   = (const float*)d_in[8];
    const float* bz   = (const float*)d_in[9];
    const float* bn_w = (const float*)d_in[10];
    const float* bn_b = (const float*)d_in[11];
    const float* gamma= (const float*)d_in[12];
    float* out = (float*)d_out;

    float *wz, *me, *vb, *beta, *scale, *shift;
    __nv_bfloat16 *x3, *Wz3;
    __half *att, *xh, *maskT, *whgm, *wT, *MT, *xM, *phm, *pm;
    cudaGetSymbolAddress((void**)&wz,    g_wz);
    cudaGetSymbolAddress((void**)&me,    g_me);
    cudaGetSymbolAddress((void**)&att,   g_att);
    cudaGetSymbolAddress((void**)&x3,    g_x3);
    cudaGetSymbolAddress((void**)&Wz3,   g_Wz3);
    cudaGetSymbolAddress((void**)&xh,    g_xh);
    cudaGetSymbolAddress((void**)&maskT, g_maskT);
    cudaGetSymbolAddress((void**)&whgm,  g_whgm);
    cudaGetSymbolAddress((void**)&wT,    g_wT);
    cudaGetSymbolAddress((void**)&MT,    g_MT);
    cudaGetSymbolAddress((void**)&xM,    g_xM);
    cudaGetSymbolAddress((void**)&phm,   g_phm);
    cudaGetSymbolAddress((void**)&pm,    g_pm);
    cudaGetSymbolAddress((void**)&vb,    g_vb);
    cudaGetSymbolAddress((void**)&beta,  g_beta);
    cudaGetSymbolAddress((void**)&scale, g_scale);
    cudaGetSymbolAddress((void**)&shift, g_shift);

    const long long EE  = (long long)EEL;
    const long long sX3 = (long long)THW * K3;
    const int SMEM_GEMM = STAGES * 32768;   // 96KB
    cudaFuncSetAttribute(gemm_f16_mma,  cudaFuncAttributeMaxDynamicSharedMemorySize, SMEM_GEMM);
    cudaFuncSetAttribute(gemm_bf16_mma, cudaFuncAttributeMaxDynamicSharedMemorySize, SMEM_GEMM);

    // side streams + fork/join events (created once on the first, non-captured call)
    static cudaStream_t s1 = nullptr, s2 = nullptr;
    static cudaEvent_t eFork = nullptr, eJoin1 = nullptr, eJoin2 = nullptr;
    if (!s1) {
        cudaStreamCreateWithFlags(&s1, cudaStreamNonBlocking);
        cudaStreamCreateWithFlags(&s2, cudaStreamNonBlocking);
        cudaEventCreateWithFlags(&eFork,  cudaEventDisableTiming);
        cudaEventCreateWithFlags(&eJoin1, cudaEventDisableTiming);
        cudaEventCreateWithFlags(&eJoin2, cudaEventDisableTiming);
    }

    const dim3 t32(32, 8);

    // ---- prep (main stream) ----
    prep_weights<<<(3 * CC * CC + CC + 255) / 256, 256>>>(Wh, Wg, Wm, bh, whgm, wT, vb);
    split_w<<<(CC * CC + 255) / 256, 256>>>(Wz, Wz3);
    // MT[a,b] = sum_j WgT[a,j]*WhT[b,j] = (Wh^T Wg)^T   (tiny GEMM)
    gemm_f16_mma<<<dim3(4, 4, 1), 256, SMEM_GEMM>>>(
        wT + CC * CC, wT, MT, 1, nullptr, nullptr, CC, CC, CC, CC, CC, 0, 0, 0, 0);
    split_x<<<dim3(THW / 32, CC / 32, NB), t32>>>(x, x3, xh, CT, sX3, CT);
    transpose_cvt<<<dim3(THW / 32, CC / 32, NB), t32>>>(mask, maskT, CT, CT);
    beta_k<<<(NB * THW * 32 + 255) / 256, 256>>>(xh, vb, beta);

    // ---- fork ----
    cudaEventRecord(eFork, 0);
    cudaStreamWaitEvent(s1, eFork, 0);
    cudaStreamWaitEvent(s2, eFork, 0);

    // side s1: pm, wz, bn_stats (needed only by softmax_final)
    gemm_f16_mma<<<dim3(THW / 128, CC / 128, NB), 256, SMEM_GEMM, s1>>>(
        whgm + 2 * CC * CC, xh, pm, 1, bm, nullptr, CC, THW, CC, CC, CC, 0, CT, CT, 0);
    gemm_bf16_mma<<<dim3(THW / 128, CC / 128, NB), 256, SMEM_GEMM, s1>>>(
        Wz3, x3, wz, bz, CC, THW, K3, K3, K3, 0, sX3, CT);
    bn_stats<<<CC, 256, 0, s1>>>(wz, bn_w, bn_b, scale, shift);
    cudaEventRecord(eJoin1, s1);

    // side s2: phm (needed only by the mask GEMM)
    gemm_f16_mma<<<dim3(THW / 128, CC / 128, NB), 256, SMEM_GEMM, s2>>>(
        whgm, maskT, phm, 1, bh, nullptr, CC, THW, CC, CC, CC, 0, CT, CT, 0);
    cudaEventRecord(eJoin2, s2);

    // ---- main chain ----
    // xM[t,k] = sum_c xh[t,c]*MT[k,c]   (f16, N=512 — half the old proj1)
    gemm_f16_mma<<<dim3(CC / 128, THW / 128, NB), 256, SMEM_GEMM>>>(
        xh, MT, xM, 1, nullptr, nullptr, THW, CC, CC, CC, CC, CT, 0, CT, 0);

    // energy[t,s] = sum_k xM[t,k]*xh[s,k] + beta[s]  (f16 out into att)
    gemm_f16_mma<<<dim3(THW / 128, THW / 128, NB), 256, SMEM_GEMM>>>(
        xM, xh, att, 1, nullptr, beta, THW, THW, CC, CC, CC, CT, CT, EE, THW);

    // attention = softmax_s(energy), f16 in place
    softmax_h<<<NB * THW, 256>>>(att, THW);

    // join phm before the mask GEMM
    cudaStreamWaitEvent(0, eJoin2, 0);

    // mask_energy[c,t] = sum_s phm[c,s]*att[t,s]  (fp32 out, f16 acc)
    gemm_f16_mma<<<dim3(THW / 128, CC / 128, NB), 256, SMEM_GEMM>>>(
        phm, att, me, 0, nullptr, nullptr, CC, THW, THW, THW, THW, CT, EE, CT, 0);

    // join side branch (pm, wz, scale/shift)
    cudaStreamWaitEvent(0, eJoin1, 0);

    // fused softmax_t(me) + final combine
    softmax_final<<<NB * CC, 256>>>(me, pm, wz, scale, shift, gamma, out);
}

// round 15
// speedup vs baseline: 1.0359x; 1.0359x over previous
#include <cuda_runtime.h>
#include <cuda_bf16.h>
#include <cuda_fp16.h>
#include <cstdint>

#define NB  2
#define CC  512
#define THW 6272
#define CT  (CC*THW)
#define EEL ((size_t)THW*(size_t)THW)
#define K3  (3*CC)                         // 1536

// ---------------- device scratch ----------------
__device__ float g_wz[NB*CT];                        // fp32 Wz projection [c,t]
__device__ float g_me[NB*CT];                        // mask_energy fp32
__device__ __half g_att [NB*EEL];                    // energy -> attention fp16 [t,s]
__device__ __nv_bfloat16 g_x3 [NB*(size_t)THW*K3];  // [t, x_hi|x_lo|x_hi] bf16 (wz branch)
__device__ __nv_bfloat16 g_Wz3[CC*K3];               // [o, hi|hi|lo] bf16
__device__ __half g_xh  [NB*CT];                     // x^T [t,c] fp16
__device__ __half g_maskT[NB*CT];                    // mask^T [s,c] fp16
__device__ __half g_whgm[3*CC*CC];                   // Wh,Wg,Wm fp16 [o,c]
__device__ __half g_wT  [2*CC*CC];                   // WhT,WgT fp16 [c,o]
__device__ __half g_MT  [CC*CC];                     // (Wh^T Wg)^T fp16 [k,c]
__device__ __half g_xM  [NB*CT];                     // x^T(Wh^T Wg) fp16 [t,k]
__device__ __half g_phm [NB*CT];                     // [c,s] fp16
__device__ __half g_pm  [NB*CT];                     // [c,t] fp16
__device__ float g_vb  [CC];                         // Wg^T bh
__device__ float g_beta[NB*THW];                     // x^T (Wg^T bh)  [s]
__device__ float g_scale[CC];
__device__ float g_shift[CC];

// ---------------- helpers ----------------
__device__ __forceinline__ uint32_t smem_u32(const void* p) {
    uint32_t a;
    asm("{ .reg .u64 t; cvta.to.shared.u64 t, %1; cvt.u32.u64 %0, t; }" : "=r"(a) : "l"(p));
    return a;
}
#define SWZ128(o) ((o) ^ (((o) >> 3) & 0x70))
__device__ __forceinline__ void cp16(uint32_t s, const void* g) {
    asm volatile("cp.async.cg.shared.global [%0], [%1], 16;" :: "r"(s), "l"(g));
}
#define CP_COMMIT() asm volatile("cp.async.commit_group;" ::: "memory")
#define CP_WAIT(n)  asm volatile("cp.async.wait_group %0;" :: "n"(n) : "memory")

__device__ __forceinline__ void ldmx4(uint32_t& r0, uint32_t& r1, uint32_t& r2, uint32_t& r3,
                                      uint32_t addr) {
    asm volatile("ldmatrix.sync.aligned.m8n8.x4.shared.b16 {%0,%1,%2,%3}, [%4];"
                 : "=r"(r0), "=r"(r1), "=r"(r2), "=r"(r3) : "r"(addr));
}
__device__ __forceinline__ void mma_bf16(float* d, const uint32_t* a, const uint32_t* b) {
    asm volatile("mma.sync.aligned.m16n8k16.row.col.f32.bf16.bf16.f32 "
                 "{%0,%1,%2,%3}, {%4,%5,%6,%7}, {%8,%9}, {%0,%1,%2,%3};"
                 : "+f"(d[0]), "+f"(d[1]), "+f"(d[2]), "+f"(d[3])
                 : "r"(a[0]), "r"(a[1]), "r"(a[2]), "r"(a[3]), "r"(b[0]), "r"(b[1]));
}
__device__ __forceinline__ void mma_f16(uint32_t* d, const uint32_t* a, const uint32_t* b) {
    asm volatile("mma.sync.aligned.m16n8k16.row.col.f16.f16.f16.f16 "
                 "{%0,%1}, {%2,%3,%4,%5}, {%6,%7}, {%0,%1};"
                 : "+r"(d[0]), "+r"(d[1])
                 : "r"(a[0]), "r"(a[1]), "r"(a[2]), "r"(a[3]), "r"(b[0]), "r"(b[1]));
}

#define STAGES 3

// ================= fp16 HMMA TN GEMM (fp16 accumulate) =================
// C[m,n] = sum_k A[m,k]*B[n,k] (+bias_m[m]) (+bias_n[z*sBiasN + n]); out_kind: 0=f32, 1=f16
__global__ void __launch_bounds__(256)
gemm_f16_mma(const __half* __restrict__ A, const __half* __restrict__ B,
             void* __restrict__ Cv, int out_kind,
             const float* __restrict__ bias_m, const float* __restrict__ bias_n,
             int M, int N, int K, int ldA, int ldB,
             long long sA, long long sB, long long sC, long long sBiasN)
{
    extern __shared__ char smem[];
    const uint32_t sb = smem_u32(smem);
    const int tid = threadIdx.x, wid = tid >> 5, lane = tid & 31;
    const int wm = wid & 1, wn = wid >> 1;
    const int m_w = wm * 64, n_w = wn * 32;

    uint32_t bufA[STAGES], bufB[STAGES];
#pragma unroll
    for (int s = 0; s < STAGES; s++) { bufA[s] = sb + s * 32768; bufB[s] = bufA[s] + 16384; }

    const int m0 = blockIdx.y * 128, n0 = blockIdx.x * 128;
    const char* Ab = (const char*)(A + (long long)blockIdx.z * sA + (long long)m0 * ldA);
    const char* Bb = (const char*)(B + (long long)blockIdx.z * sB + (long long)n0 * ldB);
    const long long rbA = (long long)ldA * 2;
    const long long rbB = (long long)ldB * 2;
    const int nc = K >> 6;

    const int lrow = tid >> 3;
    const int lcol = (tid & 7) << 4;

    auto load_chunk = [&](int c, int s) {
        const char* ga = Ab + (long long)c * 128;
        const char* gb = Bb + (long long)c * 128;
#pragma unroll
        for (int i = 0; i < 4; i++) {
            int row = lrow + i * 32;
            uint32_t off = SWZ128((uint32_t)(row * 128 + lcol));
            long long go = (long long)row;
            cp16(bufA[s] + off, ga + go * rbA + lcol);
            cp16(bufB[s] + off, gb + go * rbB + lcol);
        }
    };

    uint32_t acc[4][4][2];
#pragma unroll
    for (int i = 0; i < 4; i++)
#pragma unroll
        for (int j = 0; j < 4; j++) { acc[i][j][0] = 0u; acc[i][j][1] = 0u; }

    const int grp = lane >> 3, rw = lane & 7;
    const int a_row = (grp & 1) * 8 + rw;
    const int a_kh  = (grp >> 1) * 16;
    const int b_row = (grp >> 1) * 8 + rw;
    const int b_kh  = (grp & 1) * 16;

    load_chunk(0, 0); CP_COMMIT();
    if (nc > 1) { load_chunk(1, 1); CP_COMMIT(); }

    for (int c = 0; c < nc; c++) {
        if (c + 1 < nc) { CP_WAIT(1); } else { CP_WAIT(0); }
        __syncthreads();
        if (c + 2 < nc) { load_chunk(c + 2, (c + 2) % STAGES); CP_COMMIT(); }
        const uint32_t sa = bufA[c % STAGES], sbm = bufB[c % STAGES];
#pragma unroll
        for (int kk = 0; kk < 4; kk++) {
            const int kb = kk * 32;
            uint32_t a[4][4], b[4][2];
#pragma unroll
            for (int mt = 0; mt < 4; mt++) {
                int row = m_w + mt * 16 + a_row;
                uint32_t ad = sa + SWZ128((uint32_t)(row * 128 + kb + a_kh));
                ldmx4(a[mt][0], a[mt][1], a[mt][2], a[mt][3], ad);
            }
#pragma unroll
            for (int np = 0; np < 2; np++) {
                int row = n_w + np * 16 + b_row;
                uint32_t bd = sbm + SWZ128((uint32_t)(row * 128 + kb + b_kh));
                uint32_t r0, r1, r2, r3;
                ldmx4(r0, r1, r2, r3, bd);
                b[np * 2][0] = r0; b[np * 2][1] = r1;
                b[np * 2 + 1][0] = r2; b[np * 2 + 1][1] = r3;
            }
#pragma unroll
            for (int mt = 0; mt < 4; mt++)
#pragma unroll
                for (int nt = 0; nt < 4; nt++)
                    mma_f16(acc[mt][nt], a[mt], b[nt]);
        }
    }

    const int r_lo = lane >> 2, c_off = (lane & 3) * 2;
    const float* bnz = bias_n ? (bias_n + (long long)blockIdx.z * sBiasN) : nullptr;
#pragma unroll
    for (int mt = 0; mt < 4; mt++) {
        int row = m0 + m_w + mt * 16 + r_lo;
#pragma unroll
        for (int half = 0; half < 2; half++) {
            int r = row + half * 8;
            float bmv = bias_m ? bias_m[r] : 0.f;
            long long base = (long long)blockIdx.z * sC + (long long)r * N + n0 + n_w + c_off;
#pragma unroll
            for (int nt = 0; nt < 4; nt++) {
                float2 v = __half22float2(*reinterpret_cast<__half2*>(&acc[mt][nt][half]));
                v.x += bmv; v.y += bmv;
                int col = n0 + n_w + nt * 8 + c_off;
                if (bnz) { v.x += bnz[col]; v.y += bnz[col + 1]; }
                if (out_kind == 1) {
                    *reinterpret_cast<__half2*>((__half*)Cv + base + nt * 8) =
                        __floats2half2_rn(v.x, v.y);
                } else {
                    *reinterpret_cast<float2*>((float*)Cv + base + nt * 8) = v;
                }
            }
        }
    }
}

// ================= bf16 HMMA TN GEMM (fp32 accumulate; wz branch) =================
__global__ void __launch_bounds__(256)
gemm_bf16_mma(const __nv_bfloat16* __restrict__ A, const __nv_bfloat16* __restrict__ B,
              float* __restrict__ Cv,
              const float* __restrict__ bias_m,
              int M, int N, int K, int ldA, int ldB,
              long long sA, long long sB, long long sC)
{
    extern __shared__ char smem[];
    const uint32_t sb = smem_u32(smem);
    const int tid = threadIdx.x, wid = tid >> 5, lane = tid & 31;
    const int wm = wid & 1, wn = wid >> 1;
    const int m_w = wm * 64, n_w = wn * 32;

    uint32_t bufA[STAGES], bufB[STAGES];
#pragma unroll
    for (int s = 0; s < STAGES; s++) { bufA[s] = sb + s * 32768; bufB[s] = bufA[s] + 16384; }

    const int m0 = blockIdx.y * 128, n0 = blockIdx.x * 128;
    const char* Ab = (const char*)(A + (long long)blockIdx.z * sA + (long long)m0 * ldA);
    const char* Bb = (const char*)(B + (long long)blockIdx.z * sB + (long long)n0 * ldB);
    const long long rbA = (long long)ldA * 2;
    const long long rbB = (long long)ldB * 2;
    const int nc = K >> 6;

    const int lrow = tid >> 3;
    const int lcol = (tid & 7) << 4;

    auto load_chunk = [&](int c, int s) {
        const char* ga = Ab + (long long)c * 128;
        const char* gb = Bb + (long long)c * 128;
#pragma unroll
        for (int i = 0; i < 4; i++) {
            int row = lrow + i * 32;
            uint32_t off = SWZ128((uint32_t)(row * 128 + lcol));
            long long go = (long long)row;
            cp16(bufA[s] + off, ga + go * rbA + lcol);
            cp16(bufB[s] + off, gb + go * rbB + lcol);
        }
    };

    float acc[4][4][4];
#pragma unroll
    for (int i = 0; i < 4; i++)
#pragma unroll
        for (int j = 0; j < 4; j++)
#pragma unroll
            for (int q = 0; q < 4; q++) acc[i][j][q] = 0.f;

    const int grp = lane >> 3, rw = lane & 7;
    const int a_row = (grp & 1) * 8 + rw;
    const int a_kh  = (grp >> 1) * 16;
    const int b_row = (grp >> 1) * 8 + rw;
    const int b_kh  = (grp & 1) * 16;

    load_chunk(0, 0); CP_COMMIT();
    if (nc > 1) { load_chunk(1, 1); CP_COMMIT(); }

    for (int c = 0; c < nc; c++) {
        if (c + 1 < nc) { CP_WAIT(1); } else { CP_WAIT(0); }
        __syncthreads();
        if (c + 2 < nc) { load_chunk(c + 2, (c + 2) % STAGES); CP_COMMIT(); }
        const uint32_t sa = bufA[c % STAGES], sbm = bufB[c % STAGES];
#pragma unroll
        for (int kk = 0; kk < 4; kk++) {
            const int kb = kk * 32;
            uint32_t a[4][4], b[4][2];
#pragma unroll
            for (int mt = 0; mt < 4; mt++) {
                int row = m_w + mt * 16 + a_row;
                uint32_t ad = sa + SWZ128((uint32_t)(row * 128 + kb + a_kh));
                ldmx4(a[mt][0], a[mt][1], a[mt][2], a[mt][3], ad);
            }
#pragma unroll
            for (int np = 0; np < 2; np++) {
                int row = n_w + np * 16 + b_row;
                uint32_t bd = sbm + SWZ128((uint32_t)(row * 128 + kb + b_kh));
                uint32_t r0, r1, r2, r3;
                ldmx4(r0, r1, r2, r3, bd);
                b[np * 2][0] = r0; b[np * 2][1] = r1;
                b[np * 2 + 1][0] = r2; b[np * 2 + 1][1] = r3;
            }
#pragma unroll
            for (int mt = 0; mt < 4; mt++)
#pragma unroll
                for (int nt = 0; nt < 4; nt++)
                    mma_bf16(acc[mt][nt], a[mt], b[nt]);
        }
    }

    const int r_lo = lane >> 2, c_off = (lane & 3) * 2;
#pragma unroll
    for (int mt = 0; mt < 4; mt++) {
        int row = m0 + m_w + mt * 16 + r_lo;
#pragma unroll
        for (int half = 0; half < 2; half++) {
            int r = row + half * 8;
            float bmv = bias_m ? bias_m[r] : 0.f;
            long long base = (long long)blockIdx.z * sC + (long long)r * N + n0 + n_w + c_off;
#pragma unroll
            for (int nt = 0; nt < 4; nt++) {
                float v0 = acc[mt][nt][half * 2 + 0] + bmv;
                float v1 = acc[mt][nt][half * 2 + 1] + bmv;
                *reinterpret_cast<float2*>(Cv + base + nt * 8) = make_float2(v0, v1);
            }
        }
    }
}

// ---------------- prep: Wh,Wg,Wm -> fp16 [o,c]; WhT,WgT fp16 [c,o] ----------------
__global__ void prep_weights(const float* __restrict__ Wh, const float* __restrict__ Wg,
                             const float* __restrict__ Wm,
                             __half* __restrict__ whgm, __half* __restrict__ wT)
{
    int i = blockIdx.x * blockDim.x + threadIdx.x;
    int n = CC * CC;
    if (i < n) {
        int o = i / CC, c = i - o * CC;
        __half h = __float2half(Wh[i]);
        whgm[i] = h;
        wT[c * CC + o] = h;                    // WhT
    } else if (i < 2 * n) {
        int j = i - n;
        int o = j / CC, c = j - o * CC;
        __half h = __float2half(Wg[j]);
        whgm[i] = h;
        wT[n + c * CC + o] = h;                // WgT
    } else if (i < 3 * n) {
        whgm[i] = __float2half(Wm[i - 2 * n]);
    }
}

// ---------------- vb[c] = sum_o Wg[o,c]*bh[o]  (one warp per c) ----------------
__global__ void __launch_bounds__(256)
vb_k(const float* __restrict__ Wg, const float* __restrict__ bh, float* __restrict__ vb)
{
    int c = (blockIdx.x * blockDim.x + threadIdx.x) >> 5;
    int lane = threadIdx.x & 31;
    if (c >= CC) return;
    float s = 0.f;
#pragma unroll
    for (int i = 0; i < 16; i++) {
        int o = lane + i * 32;
        s += Wg[o * CC + c] * bh[o];
    }
#pragma unroll
    for (int o = 16; o; o >>= 1) s += __shfl_xor_sync(0xffffffffu, s, o);
    if (lane == 0) vb[c] = s;
}

// ---------------- Wz [o,c] fp32 -> Wz3 [o, hi|hi|lo] bf16 ----------------
__global__ void split_w(const float* __restrict__ in, __nv_bfloat16* __restrict__ out)
{
    int i = blockIdx.x * blockDim.x + threadIdx.x;
    if (i >= CC * CC) return;
    int o = i / CC, c = i - o * CC;
    float v = in[i];
    __nv_bfloat16 hi = __float2bfloat16(v);
    __nv_bfloat16 lo = __float2bfloat16(v - __bfloat162float(hi));
    out[(long long)o * K3 + c]          = hi;
    out[(long long)o * K3 + CC + c]     = hi;
    out[(long long)o * K3 + 2 * CC + c] = lo;
}

// ---------------- x [c,t] fp32 -> x3 bf16 [t, hi|lo|hi] AND xh fp16 [t,c] ----------------
__global__ void split_x(const float* __restrict__ in, __nv_bfloat16* __restrict__ x3,
                        __half* __restrict__ xh, long long sIn, long long sX3, long long sXh)
{
    __shared__ float tile[32][33];
    const float* ib = in + (long long)blockIdx.z * sIn;
    __nv_bfloat16* o3 = x3 + (long long)blockIdx.z * sX3;
    __half* oh = xh + (long long)blockIdx.z * sXh;
    int t0 = blockIdx.x * 32, c0 = blockIdx.y * 32;
    int x = threadIdx.x, y = threadIdx.y;
#pragma unroll
    for (int i = 0; i < 32; i += 8)
        tile[y + i][x] = ib[(long long)(c0 + y + i) * THW + t0 + x];
    __syncthreads();
#pragma unroll
    for (int i = 0; i < 32; i += 8) {
        float v = tile[x][y + i];
        __nv_bfloat16 hi = __float2bfloat16(v);
        __nv_bfloat16 lo = __float2bfloat16(v - __bfloat162float(hi));
        long long row = (long long)(t0 + y + i) * K3;
        o3[row + c0 + x]          = hi;
        o3[row + CC + c0 + x]     = lo;
        o3[row + 2 * CC + c0 + x] = hi;
        oh[(long long)(t0 + y + i) * CC + c0 + x] = __float2half(v);
    }
}

// ---------------- transpose + fp32->fp16 (mask^T) ----------------
__global__ void transpose_cvt(const float* __restrict__ in, __half* __restrict__ out,
                              long long sIn, long long sOut)
{
    __shared__ float tile[32][33];
    const float* ib = in + (long long)blockIdx.z * sIn;
    __half* ob = out + (long long)blockIdx.z * sOut;
    int t0 = blockIdx.x * 32, c0 = blockIdx.y * 32;
    int x = threadIdx.x, y = threadIdx.y;
#pragma unroll
    for (int i = 0; i < 32; i += 8)
        tile[y + i][x] = ib[(long long)(c0 + y + i) * THW + t0 + x];
    __syncthreads();
#pragma unroll
    for (int i = 0; i < 32; i += 8)
        ob[(long long)(t0 + y + i) * CC + c0 + x] = __float2half(tile[x][y + i]);
}

// ---------------- beta[z][s] = sum_c xh[z][s,c] * vb[c]  (one warp per row) ----------------
__global__ void __launch_bounds__(256)
beta_k(const __half* __restrict__ xh, const float* __restrict__ vb,
       float* __restrict__ beta)
{
    int wrow = (blockIdx.x * blockDim.x + threadIdx.x) >> 5;
    int lane = threadIdx.x & 31;
    if (wrow >= NB * THW) return;
    const __half* p = xh + (long long)wrow * CC;
    float s = 0.f;
#pragma unroll
    for (int i = 0; i < 16; i++) {
        int c = lane + i * 32;
        s += __half2float(p[c]) * vb[c];
    }
#pragma unroll
    for (int o = 16; o; o >>= 1) s += __shfl_xor_sync(0xffffffffu, s, o);
    if (lane == 0) beta[wrow] = s;
}

// ---------------- softmax fp16 in-place (attention) ----------------
__global__ void __launch_bounds__(256)
softmax_h(__half* __restrict__ data, int rowlen)
{
    __half* p = data + (long long)blockIdx.x * rowlen;
    const int tid = threadIdx.x;
    __shared__ float red[8];

    float v[25];
    float mx = -3.0e38f;
#pragma unroll
    for (int i = 0; i < 25; i++) {
        int idx = tid + (i << 8);
        v[i] = (idx < rowlen) ? __half2float(p[idx]) : -3.0e38f;
        mx = fmaxf(mx, v[i]);
    }
#pragma unroll
    for (int o = 16; o; o >>= 1) mx = fmaxf(mx, __shfl_xor_sync(0xffffffffu, mx, o));
    if ((tid & 31) == 0) red[tid >> 5] = mx;
    __syncthreads();
    mx = red[0];
#pragma unroll
    for (int w = 1; w < 8; w++) mx = fmaxf(mx, red[w]);
    __syncthreads();

    float s = 0.f;
#pragma unroll
    for (int i = 0; i < 25; i++) { v[i] = __expf(v[i] - mx); s += v[i]; }
#pragma unroll
    for (int o = 16; o; o >>= 1) s += __shfl_xor_sync(0xffffffffu, s, o);
    if ((tid & 31) == 0) red[tid >> 5] = s;
    __syncthreads();
    s = 0.f;
#pragma unroll
    for (int w = 0; w < 8; w++) s += red[w];
    float inv = 1.f / s;
#pragma unroll
    for (int i = 0; i < 25; i++) {
        int idx = tid + (i << 8);
        if (idx < rowlen) p[idx] = __float2half(v[i] * inv);
    }
}

// ---------------- BN stats on g_wz ----------------
__global__ void __launch_bounds__(256)
bn_stats(const float* __restrict__ wz, const float* __restrict__ bn_w,
         const float* __restrict__ bn_b, float* __restrict__ scale,
         float* __restrict__ shift)
{
    int c = blockIdx.x;
    int tid = threadIdx.x;
    float s = 0.f, sq = 0.f;
    for (int i = tid; i < NB * THW; i += 256) {
        int n = i / THW, t = i - n * THW;
        float v = wz[(long long)n * CT + (long long)c * THW + t];
        s += v;
        sq = fmaf(v, v, sq);
    }
    __shared__ float r1[8], r2[8];
#pragma unroll
    for (int o = 16; o; o >>= 1) {
        s  += __shfl_xor_sync(0xffffffffu, s,  o);
        sq += __shfl_xor_sync(0xffffffffu, sq, o);
    }
    if ((tid & 31) == 0) { r1[tid >> 5] = s; r2[tid >> 5] = sq; }
    __syncthreads();
    if (tid == 0) {
        s = 0.f; sq = 0.f;
#pragma unroll
        for (int w = 0; w < 8; w++) { s += r1[w]; sq += r2[w]; }
        const float invn = 1.f / (float)(NB * THW);
        float mu  = s * invn;
        float var = sq * invn - mu * mu;
        float sc  = bn_w[c] * rsqrtf(var + 1e-5f);
        scale[c] = sc;
        shift[c] = bn_b[c] - mu * sc;
    }
}

// ---------------- fused: mask_atten = softmax_t(me); out = gamma*pm*mask_atten + BN(wz) ----------------
__global__ void __launch_bounds__(256)
softmax_final(const float* __restrict__ me, const __half* __restrict__ pm,
              const float* __restrict__ wz, const float* __restrict__ scale,
              const float* __restrict__ shift, const float* __restrict__ gamma,
              float* __restrict__ out)
{
    const int blk = blockIdx.x;
    const int c = blk % CC;
    const long long base = (long long)blk * THW;
    const float* p = me + base;
    const int tid = threadIdx.x;
    __shared__ float red[8];

    float v[25];
    float mx = -3.0e38f;
#pragma unroll
    for (int i = 0; i < 25; i++) {
        int idx = tid + (i << 8);
        v[i] = (idx < THW) ? p[idx] : -3.0e38f;
        mx = fmaxf(mx, v[i]);
    }
#pragma unroll
    for (int o = 16; o; o >>= 1) mx = fmaxf(mx, __shfl_xor_sync(0xffffffffu, mx, o));
    if ((tid & 31) == 0) red[tid >> 5] = mx;
    __syncthreads();
    mx = red[0];
#pragma unroll
    for (int w = 1; w < 8; w++) mx = fmaxf(mx, red[w]);
    __syncthreads();

    float s = 0.f;
#pragma unroll
    for (int i = 0; i < 25; i++) { v[i] = __expf(v[i] - mx); s += v[i]; }
#pragma unroll
    for (int o = 16; o; o >>= 1) s += __shfl_xor_sync(0xffffffffu, s, o);
    if ((tid & 31) == 0) red[tid >> 5] = s;
    __syncthreads();
    s = 0.f;
#pragma unroll
    for (int w = 0; w < 8; w++) s += red[w];

    const float inv = 1.f / s;
    const float g  = gamma[0];
    const float sc = scale[c], sh = shift[c];
#pragma unroll
    for (int i = 0; i < 25; i++) {
        int idx = tid + (i << 8);
        if (idx < THW) {
            float ma  = v[i] * inv;
            float pmv = __half2float(pm[base + idx]);
            out[base + idx] = g * pmv * ma + fmaf(wz[base + idx], sc, sh);
        }
    }
}

// ---------------- launch ----------------
extern "C" void kernel_launch(void* const* d_in, const int* in_sizes, int n_in,
                              void* d_out, int out_size)
{
    const float* x    = (const float*)d_in[0];
    const float* mask = (const float*)d_in[1];
    const float* Wh   = (const float*)d_in[2];
    const float* bh   = (const float*)d_in[3];
    const float* Wg   = (const float*)d_in[4];
    const float* bg   = (const float*)d_in[5];
    const float* Wm   = (const float*)d_in[6];
    const float* bm   = (const float*)d_in[7];
    const float* Wz   = (const float*)d_in[8];
    const float* bz   = (const float*)d_in[9];
    const float* bn_w = (const float*)d_in[10];
    const float* bn_b = (const float*)d_in[11];
    const float* gamma= (const float*)d_in[12];
    float* out = (float*)d_out;

    float *wz, *me, *vb, *beta, *scale, *shift;
    __nv_bfloat16 *x3, *Wz3;
    __half *att, *xh, *maskT, *whgm, *wT, *MT, *xM, *phm, *pm;
    cudaGetSymbolAddress((void**)&wz,    g_wz);
    cudaGetSymbolAddress((void**)&me,    g_me);
    cudaGetSymbolAddress((void**)&att,   g_att);
    cudaGetSymbolAddress((void**)&x3,    g_x3);
    cudaGetSymbolAddress((void**)&Wz3,   g_Wz3);
    cudaGetSymbolAddress((void**)&xh,    g_xh);
    cudaGetSymbolAddress((void**)&maskT, g_maskT);
    cudaGetSymbolAddress((void**)&whgm,  g_whgm);
    cudaGetSymbolAddress((void**)&wT,    g_wT);
    cudaGetSymbolAddress((void**)&MT,    g_MT);
    cudaGetSymbolAddress((void**)&xM,    g_xM);
    cudaGetSymbolAddress((void**)&phm,   g_phm);
    cudaGetSymbolAddress((void**)&pm,    g_pm);
    cudaGetSymbolAddress((void**)&vb,    g_vb);
    cudaGetSymbolAddress((void**)&beta,  g_beta);
    cudaGetSymbolAddress((void**)&scale, g_scale);
    cudaGetSymbolAddress((void**)&shift, g_shift);

    const long long EE  = (long long)EEL;
    const long long sX3 = (long long)THW * K3;
    const int SMEM_GEMM = STAGES * 32768;   // 96KB
    cudaFuncSetAttribute(gemm_f16_mma,  cudaFuncAttributeMaxDynamicSharedMemorySize, SMEM_GEMM);
    cudaFuncSetAttribute(gemm_bf16_mma, cudaFuncAttributeMaxDynamicSharedMemorySize, SMEM_GEMM);

    // streams/events (created once on the first, non-captured call)
    static cudaStream_t s1 = nullptr, s2 = nullptr, s3 = nullptr;
    static cudaEvent_t eFork = nullptr, eX = nullptr, eW = nullptr, eBeta = nullptr,
                       ePhm = nullptr, eSide = nullptr, ePrep = nullptr;
    if (!s1) {
        cudaStreamCreateWithFlags(&s1, cudaStreamNonBlocking);
        cudaStreamCreateWithFlags(&s2, cudaStreamNonBlocking);
        cudaStreamCreateWithFlags(&s3, cudaStreamNonBlocking);
        cudaEventCreateWithFlags(&eFork, cudaEventDisableTiming);
        cudaEventCreateWithFlags(&eX,    cudaEventDisableTiming);
        cudaEventCreateWithFlags(&eW,    cudaEventDisableTiming);
        cudaEventCreateWithFlags(&eBeta, cudaEventDisableTiming);
        cudaEventCreateWithFlags(&ePhm,  cudaEventDisableTiming);
        cudaEventCreateWithFlags(&eSide, cudaEventDisableTiming);
        cudaEventCreateWithFlags(&ePrep, cudaEventDisableTiming);
    }

    const dim3 t32(32, 8);

    // ---- fork FIRST: all side streams begin by waiting on an event recorded
    //      in the capturing (default) stream, so they join the capture graph ----
    cudaEventRecord(eFork, 0);
    cudaStreamWaitEvent(s1, eFork, 0);
    cudaStreamWaitEvent(s2, eFork, 0);
    cudaStreamWaitEvent(s3, eFork, 0);

    // ---- main: critical x transform ----
    split_x<<<dim3(THW / 32, CC / 32, NB), t32>>>(x, x3, xh, CT, sX3, CT);
    cudaEventRecord(eX, 0);

    // ---- s1: weight prep -> MT; then beta (needs xh) ----
    vb_k<<<(CC * 32 + 255) / 256, 256, 0, s1>>>(Wg, bh, vb);
    prep_weights<<<(3 * CC * CC + 255) / 256, 256, 0, s1>>>(Wh, Wg, Wm, whgm, wT);
    split_w<<<(CC * CC + 255) / 256, 256, 0, s1>>>(Wz, Wz3);
    cudaEventRecord(ePrep, s1);
    // MT[a,b] = sum_j WgT[a,j]*WhT[b,j] = (Wh^T Wg)^T
    gemm_f16_mma<<<dim3(4, 4, 1), 256, SMEM_GEMM, s1>>>(
        wT + CC * CC, wT, MT, 1, nullptr, nullptr, CC, CC, CC, CC, CC, 0, 0, 0, 0);
    cudaEventRecord(eW, s1);
    cudaStreamWaitEvent(s1, eX, 0);
    beta_k<<<(NB * THW * 32 + 255) / 256, 256, 0, s1>>>(xh, vb, beta);
    cudaEventRecord(eBeta, s1);

    // ---- s2: mask transform -> phm ----
    transpose_cvt<<<dim3(THW / 32, CC / 32, NB), t32, 0, s2>>>(mask, maskT, CT, CT);
    cudaStreamWaitEvent(s2, ePrep, 0);
    gemm_f16_mma<<<dim3(THW / 128, CC / 128, NB), 256, SMEM_GEMM, s2>>>(
        whgm, maskT, phm, 1, bh, nullptr, CC, THW, CC, CC, CC, 0, CT, CT, 0);
    cudaEventRecord(ePhm, s2);

    // ---- s3: pm, wz, bn_stats ----
    cudaStreamWaitEvent(s3, eX, 0);
    cudaStreamWaitEvent(s3, ePrep, 0);
    gemm_f16_mma<<<dim3(THW / 128, CC / 128, NB), 256, SMEM_GEMM, s3>>>(
        whgm + 2 * CC * CC, xh, pm, 1, bm, nullptr, CC, THW, CC, CC, CC, 0, CT, CT, 0);
    gemm_bf16_mma<<<dim3(THW / 128, CC / 128, NB), 256, SMEM_GEMM, s3>>>(
        Wz3, x3, wz, bz, CC, THW, K3, K3, K3, 0, sX3, CT);
    bn_stats<<<CC, 256, 0, s3>>>(wz, bn_w, bn_b, scale, shift);
    cudaEventRecord(eSide, s3);

    // ---- main chain ----
    cudaStreamWaitEvent(0, eW, 0);
    // xM[t,k] = sum_c xh[t,c]*MT[k,c]
    gemm_f16_mma<<<dim3(CC / 128, THW / 128, NB), 256, SMEM_GEMM>>>(
        xh, MT, xM, 1, nullptr, nullptr, THW, CC, CC, CC, CC, CT, 0, CT, 0);

    cudaStreamWaitEvent(0, eBeta, 0);
    // energy[t,s] = sum_k xM[t,k]*xh[s,k] + beta[s]
    gemm_f16_mma<<<dim3(THW / 128, THW / 128, NB), 256, SMEM_GEMM>>>(
        xM, xh, att, 1, nullptr, beta, THW, THW, CC, CC, CC, CT, CT, EE, THW);

    softmax_h<<<NB * THW, 256>>>(att, THW);

    cudaStreamWaitEvent(0, ePhm, 0);
    // mask_energy[c,t] = sum_s phm[c,s]*att[t,s]
    gemm_f16_mma<<<dim3(THW / 128, CC / 128, NB), 256, SMEM_GEMM>>>(
        phm, att, me, 0, nullptr, nullptr, CC, THW, THW, THW, THW, CT, EE, CT, 0);

    cudaStreamWaitEvent(0, eSide, 0);
    softmax_final<<<NB * CC, 256>>>(me, pm, wz, scale, shift, gamma, out);
}

// round 16
// speedup vs baseline: 1.0934x; 1.0555x over previous
#include <cuda_runtime.h>
#include <cuda_fp16.h>
#include <cstdint>

#define NB  2
#define CC  512
#define THW 6272
#define CT  (CC*THW)
#define EEL ((size_t)THW*(size_t)THW)

// ---------------- device scratch ----------------
__device__ float g_wz[NB*CT];                        // fp32 Wz projection [c,t]
__device__ float g_me[NB*CT];                        // mask_energy fp32
__device__ __half g_att [NB*EEL];                    // energy -> attention fp16 [t,s]
__device__ __half g_xh  [NB*CT];                     // x^T [t,c] fp16
__device__ __half g_maskT[NB*CT];                    // mask^T [s,c] fp16
__device__ __half g_whgm[4*CC*CC];                   // Wh,Wg,Wm,Wz fp16 [o,c]
__device__ __half g_wT  [2*CC*CC];                   // WhT,WgT fp16 [c,o]
__device__ __half g_MT  [CC*CC];                     // (Wh^T Wg)^T fp16 [k,c]
__device__ __half g_xM  [NB*CT];                     // x^T(Wh^T Wg) fp16 [t,k]
__device__ __half g_phm [NB*CT];                     // [c,s] fp16
__device__ __half g_pm  [NB*CT];                     // [c,t] fp16
__device__ float g_vb  [CC];                         // Wg^T bh
__device__ float g_beta[NB*THW];                     // x^T (Wg^T bh)  [s]
__device__ float g_scale[CC];
__device__ float g_shift[CC];

// ---------------- helpers ----------------
__device__ __forceinline__ uint32_t smem_u32(const void* p) {
    uint32_t a;
    asm("{ .reg .u64 t; cvta.to.shared.u64 t, %1; cvt.u32.u64 %0, t; }" : "=r"(a) : "l"(p));
    return a;
}
#define SWZ128(o) ((o) ^ (((o) >> 3) & 0x70))
__device__ __forceinline__ void cp16(uint32_t s, const void* g) {
    asm volatile("cp.async.cg.shared.global [%0], [%1], 16;" :: "r"(s), "l"(g));
}
#define CP_COMMIT() asm volatile("cp.async.commit_group;" ::: "memory")
#define CP_WAIT(n)  asm volatile("cp.async.wait_group %0;" :: "n"(n) : "memory")

__device__ __forceinline__ void ldmx4(uint32_t& r0, uint32_t& r1, uint32_t& r2, uint32_t& r3,
                                      uint32_t addr) {
    asm volatile("ldmatrix.sync.aligned.m8n8.x4.shared.b16 {%0,%1,%2,%3}, [%4];"
                 : "=r"(r0), "=r"(r1), "=r"(r2), "=r"(r3) : "r"(addr));
}
__device__ __forceinline__ void mma_f16f32(float* d, const uint32_t* a, const uint32_t* b) {
    asm volatile("mma.sync.aligned.m16n8k16.row.col.f32.f16.f16.f32 "
                 "{%0,%1,%2,%3}, {%4,%5,%6,%7}, {%8,%9}, {%0,%1,%2,%3};"
                 : "+f"(d[0]), "+f"(d[1]), "+f"(d[2]), "+f"(d[3])
                 : "r"(a[0]), "r"(a[1]), "r"(a[2]), "r"(a[3]), "r"(b[0]), "r"(b[1]));
}
__device__ __forceinline__ void mma_f16(uint32_t* d, const uint32_t* a, const uint32_t* b) {
    asm volatile("mma.sync.aligned.m16n8k16.row.col.f16.f16.f16.f16 "
                 "{%0,%1}, {%2,%3,%4,%5}, {%6,%7}, {%0,%1};"
                 : "+r"(d[0]), "+r"(d[1])
                 : "r"(a[0]), "r"(a[1]), "r"(a[2]), "r"(a[3]), "r"(b[0]), "r"(b[1]));
}

#define STAGES 3

// ================= fp16 HMMA TN GEMM (fp16 accumulate) =================
// C[m,n] = sum_k A[m,k]*B[n,k] (+bias_m[m]) (+bias_n[z*sBiasN + n]); out_kind: 0=f32, 1=f16
__global__ void __launch_bounds__(256)
gemm_f16_mma(const __half* __restrict__ A, const __half* __restrict__ B,
             void* __restrict__ Cv, int out_kind,
             const float* __restrict__ bias_m, const float* __restrict__ bias_n,
             int M, int N, int K, int ldA, int ldB,
             long long sA, long long sB, long long sC, long long sBiasN)
{
    extern __shared__ char smem[];
    const uint32_t sb = smem_u32(smem);
    const int tid = threadIdx.x, wid = tid >> 5, lane = tid & 31;
    const int wm = wid & 1, wn = wid >> 1;
    const int m_w = wm * 64, n_w = wn * 32;

    uint32_t bufA[STAGES], bufB[STAGES];
#pragma unroll
    for (int s = 0; s < STAGES; s++) { bufA[s] = sb + s * 32768; bufB[s] = bufA[s] + 16384; }

    const int m0 = blockIdx.y * 128, n0 = blockIdx.x * 128;
    const char* Ab = (const char*)(A + (long long)blockIdx.z * sA + (long long)m0 * ldA);
    const char* Bb = (const char*)(B + (long long)blockIdx.z * sB + (long long)n0 * ldB);
    const long long rbA = (long long)ldA * 2;
    const long long rbB = (long long)ldB * 2;
    const int nc = K >> 6;

    const int lrow = tid >> 3;
    const int lcol = (tid & 7) << 4;

    auto load_chunk = [&](int c, int s) {
        const char* ga = Ab + (long long)c * 128;
        const char* gb = Bb + (long long)c * 128;
#pragma unroll
        for (int i = 0; i < 4; i++) {
            int row = lrow + i * 32;
            uint32_t off = SWZ128((uint32_t)(row * 128 + lcol));
            long long go = (long long)row;
            cp16(bufA[s] + off, ga + go * rbA + lcol);
            cp16(bufB[s] + off, gb + go * rbB + lcol);
        }
    };

    uint32_t acc[4][4][2];
#pragma unroll
    for (int i = 0; i < 4; i++)
#pragma unroll
        for (int j = 0; j < 4; j++) { acc[i][j][0] = 0u; acc[i][j][1] = 0u; }

    const int grp = lane >> 3, rw = lane & 7;
    const int a_row = (grp & 1) * 8 + rw;
    const int a_kh  = (grp >> 1) * 16;
    const int b_row = (grp >> 1) * 8 + rw;
    const int b_kh  = (grp & 1) * 16;

    load_chunk(0, 0); CP_COMMIT();
    if (nc > 1) { load_chunk(1, 1); CP_COMMIT(); }

    for (int c = 0; c < nc; c++) {
        if (c + 1 < nc) { CP_WAIT(1); } else { CP_WAIT(0); }
        __syncthreads();
        if (c + 2 < nc) { load_chunk(c + 2, (c + 2) % STAGES); CP_COMMIT(); }
        const uint32_t sa = bufA[c % STAGES], sbm = bufB[c % STAGES];
#pragma unroll
        for (int kk = 0; kk < 4; kk++) {
            const int kb = kk * 32;
            uint32_t a[4][4], b[4][2];
#pragma unroll
            for (int mt = 0; mt < 4; mt++) {
                int row = m_w + mt * 16 + a_row;
                uint32_t ad = sa + SWZ128((uint32_t)(row * 128 + kb + a_kh));
                ldmx4(a[mt][0], a[mt][1], a[mt][2], a[mt][3], ad);
            }
#pragma unroll
            for (int np = 0; np < 2; np++) {
                int row = n_w + np * 16 + b_row;
                uint32_t bd = sbm + SWZ128((uint32_t)(row * 128 + kb + b_kh));
                uint32_t r0, r1, r2, r3;
                ldmx4(r0, r1, r2, r3, bd);
                b[np * 2][0] = r0; b[np * 2][1] = r1;
                b[np * 2 + 1][0] = r2; b[np * 2 + 1][1] = r3;
            }
#pragma unroll
            for (int mt = 0; mt < 4; mt++)
#pragma unroll
                for (int nt = 0; nt < 4; nt++)
                    mma_f16(acc[mt][nt], a[mt], b[nt]);
        }
    }

    const int r_lo = lane >> 2, c_off = (lane & 3) * 2;
    const float* bnz = bias_n ? (bias_n + (long long)blockIdx.z * sBiasN) : nullptr;
#pragma unroll
    for (int mt = 0; mt < 4; mt++) {
        int row = m0 + m_w + mt * 16 + r_lo;
#pragma unroll
        for (int half = 0; half < 2; half++) {
            int r = row + half * 8;
            float bmv = bias_m ? bias_m[r] : 0.f;
            long long base = (long long)blockIdx.z * sC + (long long)r * N + n0 + n_w + c_off;
#pragma unroll
            for (int nt = 0; nt < 4; nt++) {
                float2 v = __half22float2(*reinterpret_cast<__half2*>(&acc[mt][nt][half]));
                v.x += bmv; v.y += bmv;
                int col = n0 + n_w + nt * 8 + c_off;
                if (bnz) { v.x += bnz[col]; v.y += bnz[col + 1]; }
                if (out_kind == 1) {
                    *reinterpret_cast<__half2*>((__half*)Cv + base + nt * 8) =
                        __floats2half2_rn(v.x, v.y);
                } else {
                    *reinterpret_cast<float2*>((float*)Cv + base + nt * 8) = v;
                }
            }
        }
    }
}

// ================= fp16 HMMA TN GEMM with fp32 accumulate (wz branch) =================
__global__ void __launch_bounds__(256)
gemm_f16_f32acc(const __half* __restrict__ A, const __half* __restrict__ B,
                float* __restrict__ Cv, const float* __restrict__ bias_m,
                int M, int N, int K, int ldA, int ldB,
                long long sA, long long sB, long long sC)
{
    extern __shared__ char smem[];
    const uint32_t sb = smem_u32(smem);
    const int tid = threadIdx.x, wid = tid >> 5, lane = tid & 31;
    const int wm = wid & 1, wn = wid >> 1;
    const int m_w = wm * 64, n_w = wn * 32;

    uint32_t bufA[STAGES], bufB[STAGES];
#pragma unroll
    for (int s = 0; s < STAGES; s++) { bufA[s] = sb + s * 32768; bufB[s] = bufA[s] + 16384; }

    const int m0 = blockIdx.y * 128, n0 = blockIdx.x * 128;
    const char* Ab = (const char*)(A + (long long)blockIdx.z * sA + (long long)m0 * ldA);
    const char* Bb = (const char*)(B + (long long)blockIdx.z * sB + (long long)n0 * ldB);
    const long long rbA = (long long)ldA * 2;
    const long long rbB = (long long)ldB * 2;
    const int nc = K >> 6;

    const int lrow = tid >> 3;
    const int lcol = (tid & 7) << 4;

    auto load_chunk = [&](int c, int s) {
        const char* ga = Ab + (long long)c * 128;
        const char* gb = Bb + (long long)c * 128;
#pragma unroll
        for (int i = 0; i < 4; i++) {
            int row = lrow + i * 32;
            uint32_t off = SWZ128((uint32_t)(row * 128 + lcol));
            long long go = (long long)row;
            cp16(bufA[s] + off, ga + go * rbA + lcol);
            cp16(bufB[s] + off, gb + go * rbB + lcol);
        }
    };

    float acc[4][4][4];
#pragma unroll
    for (int i = 0; i < 4; i++)
#pragma unroll
        for (int j = 0; j < 4; j++)
#pragma unroll
            for (int q = 0; q < 4; q++) acc[i][j][q] = 0.f;

    const int grp = lane >> 3, rw = lane & 7;
    const int a_row = (grp & 1) * 8 + rw;
    const int a_kh  = (grp >> 1) * 16;
    const int b_row = (grp >> 1) * 8 + rw;
    const int b_kh  = (grp & 1) * 16;

    load_chunk(0, 0); CP_COMMIT();
    if (nc > 1) { load_chunk(1, 1); CP_COMMIT(); }

    for (int c = 0; c < nc; c++) {
        if (c + 1 < nc) { CP_WAIT(1); } else { CP_WAIT(0); }
        __syncthreads();
        if (c + 2 < nc) { load_chunk(c + 2, (c + 2) % STAGES); CP_COMMIT(); }
        const uint32_t sa = bufA[c % STAGES], sbm = bufB[c % STAGES];
#pragma unroll
        for (int kk = 0; kk < 4; kk++) {
            const int kb = kk * 32;
            uint32_t a[4][4], b[4][2];
#pragma unroll
            for (int mt = 0; mt < 4; mt++) {
                int row = m_w + mt * 16 + a_row;
                uint32_t ad = sa + SWZ128((uint32_t)(row * 128 + kb + a_kh));
                ldmx4(a[mt][0], a[mt][1], a[mt][2], a[mt][3], ad);
            }
#pragma unroll
            for (int np = 0; np < 2; np++) {
                int row = n_w + np * 16 + b_row;
                uint32_t bd = sbm + SWZ128((uint32_t)(row * 128 + kb + b_kh));
                uint32_t r0, r1, r2, r3;
                ldmx4(r0, r1, r2, r3, bd);
                b[np * 2][0] = r0; b[np * 2][1] = r1;
                b[np * 2 + 1][0] = r2; b[np * 2 + 1][1] = r3;
            }
#pragma unroll
            for (int mt = 0; mt < 4; mt++)
#pragma unroll
                for (int nt = 0; nt < 4; nt++)
                    mma_f16f32(acc[mt][nt], a[mt], b[nt]);
        }
    }

    const int r_lo = lane >> 2, c_off = (lane & 3) * 2;
#pragma unroll
    for (int mt = 0; mt < 4; mt++) {
        int row = m0 + m_w + mt * 16 + r_lo;
#pragma unroll
        for (int half = 0; half < 2; half++) {
            int r = row + half * 8;
            float bmv = bias_m ? bias_m[r] : 0.f;
            long long base = (long long)blockIdx.z * sC + (long long)r * N + n0 + n_w + c_off;
#pragma unroll
            for (int nt = 0; nt < 4; nt++) {
                float v0 = acc[mt][nt][half * 2 + 0] + bmv;
                float v1 = acc[mt][nt][half * 2 + 1] + bmv;
                *reinterpret_cast<float2*>(Cv + base + nt * 8) = make_float2(v0, v1);
            }
        }
    }
}

// ---------------- prep: Wh,Wg,Wm,Wz -> fp16 [o,c]; WhT,WgT fp16 [c,o] ----------------
__global__ void prep_weights(const float* __restrict__ Wh, const float* __restrict__ Wg,
                             const float* __restrict__ Wm, const float* __restrict__ Wz,
                             __half* __restrict__ whgm, __half* __restrict__ wT)
{
    int i = blockIdx.x * blockDim.x + threadIdx.x;
    int n = CC * CC;
    if (i < n) {
        int o = i / CC, c = i - o * CC;
        __half h = __float2half(Wh[i]);
        whgm[i] = h;
        wT[c * CC + o] = h;                    // WhT
    } else if (i < 2 * n) {
        int j = i - n;
        int o = j / CC, c = j - o * CC;
        __half h = __float2half(Wg[j]);
        whgm[i] = h;
        wT[n + c * CC + o] = h;                // WgT
    } else if (i < 3 * n) {
        whgm[i] = __float2half(Wm[i - 2 * n]);
    } else if (i < 4 * n) {
        whgm[i] = __float2half(Wz[i - 3 * n]);
    }
}

// ---------------- vb[c] = sum_o Wg[o,c]*bh[o]  (one warp per c) ----------------
__global__ void __launch_bounds__(256)
vb_k(const float* __restrict__ Wg, const float* __restrict__ bh, float* __restrict__ vb)
{
    int c = (blockIdx.x * blockDim.x + threadIdx.x) >> 5;
    int lane = threadIdx.x & 31;
    if (c >= CC) return;
    float s = 0.f;
#pragma unroll
    for (int i = 0; i < 16; i++) {
        int o = lane + i * 32;
        s += Wg[o * CC + c] * bh[o];
    }
#pragma unroll
    for (int o = 16; o; o >>= 1) s += __shfl_xor_sync(0xffffffffu, s, o);
    if (lane == 0) vb[c] = s;
}

// ---------------- transpose + fp32->fp16 ([c,t] -> [t,c]) ----------------
__global__ void transpose_cvt(const float* __restrict__ in, __half* __restrict__ out,
                              long long sIn, long long sOut)
{
    __shared__ float tile[32][33];
    const float* ib = in + (long long)blockIdx.z * sIn;
    __half* ob = out + (long long)blockIdx.z * sOut;
    int t0 = blockIdx.x * 32, c0 = blockIdx.y * 32;
    int x = threadIdx.x, y = threadIdx.y;
#pragma unroll
    for (int i = 0; i < 32; i += 8)
        tile[y + i][x] = ib[(long long)(c0 + y + i) * THW + t0 + x];
    __syncthreads();
#pragma unroll
    for (int i = 0; i < 32; i += 8)
        ob[(long long)(t0 + y + i) * CC + c0 + x] = __float2half(tile[x][y + i]);
}

// ---------------- beta[z][s] = sum_c xh[z][s,c] * vb[c]  (one warp per row) ----------------
__global__ void __launch_bounds__(256)
beta_k(const __half* __restrict__ xh, const float* __restrict__ vb,
       float* __restrict__ beta)
{
    int wrow = (blockIdx.x * blockDim.x + threadIdx.x) >> 5;
    int lane = threadIdx.x & 31;
    if (wrow >= NB * THW) return;
    const __half* p = xh + (long long)wrow * CC;
    float s = 0.f;
#pragma unroll
    for (int i = 0; i < 16; i++) {
        int c = lane + i * 32;
        s += __half2float(p[c]) * vb[c];
    }
#pragma unroll
    for (int o = 16; o; o >>= 1) s += __shfl_xor_sync(0xffffffffu, s, o);
    if (lane == 0) beta[wrow] = s;
}

// ---------------- softmax fp16 in-place (attention) ----------------
__global__ void __launch_bounds__(256)
softmax_h(__half* __restrict__ data, int rowlen)
{
    __half* p = data + (long long)blockIdx.x * rowlen;
    const int tid = threadIdx.x;
    __shared__ float red[8];

    float v[25];
    float mx = -3.0e38f;
#pragma unroll
    for (int i = 0; i < 25; i++) {
        int idx = tid + (i << 8);
        v[i] = (idx < rowlen) ? __half2float(p[idx]) : -3.0e38f;
        mx = fmaxf(mx, v[i]);
    }
#pragma unroll
    for (int o = 16; o; o >>= 1) mx = fmaxf(mx, __shfl_xor_sync(0xffffffffu, mx, o));
    if ((tid & 31) == 0) red[tid >> 5] = mx;
    __syncthreads();
    mx = red[0];
#pragma unroll
    for (int w = 1; w < 8; w++) mx = fmaxf(mx, red[w]);
    __syncthreads();

    float s = 0.f;
#pragma unroll
    for (int i = 0; i < 25; i++) { v[i] = __expf(v[i] - mx); s += v[i]; }
#pragma unroll
    for (int o = 16; o; o >>= 1) s += __shfl_xor_sync(0xffffffffu, s, o);
    if ((tid & 31) == 0) red[tid >> 5] = s;
    __syncthreads();
    s = 0.f;
#pragma unroll
    for (int w = 0; w < 8; w++) s += red[w];
    float inv = 1.f / s;
#pragma unroll
    for (int i = 0; i < 25; i++) {
        int idx = tid + (i << 8);
        if (idx < rowlen) p[idx] = __float2half(v[i] * inv);
    }
}

// ---------------- BN stats on g_wz ----------------
__global__ void __launch_bounds__(256)
bn_stats(const float* __restrict__ wz, const float* __restrict__ bn_w,
         const float* __restrict__ bn_b, float* __restrict__ scale,
         float* __restrict__ shift)
{
    int c = blockIdx.x;
    int tid = threadIdx.x;
    float s = 0.f, sq = 0.f;
    for (int i = tid; i < NB * THW; i += 256) {
        int n = i / THW, t = i - n * THW;
        float v = wz[(long long)n * CT + (long long)c * THW + t];
        s += v;
        sq = fmaf(v, v, sq);
    }
    __shared__ float r1[8], r2[8];
#pragma unroll
    for (int o = 16; o; o >>= 1) {
        s  += __shfl_xor_sync(0xffffffffu, s,  o);
        sq += __shfl_xor_sync(0xffffffffu, sq, o);
    }
    if ((tid & 31) == 0) { r1[tid >> 5] = s; r2[tid >> 5] = sq; }
    __syncthreads();
    if (tid == 0) {
        s = 0.f; sq = 0.f;
#pragma unroll
        for (int w = 0; w < 8; w++) { s += r1[w]; sq += r2[w]; }
        const float invn = 1.f / (float)(NB * THW);
        float mu  = s * invn;
        float var = sq * invn - mu * mu;
        float sc  = bn_w[c] * rsqrtf(var + 1e-5f);
        scale[c] = sc;
        shift[c] = bn_b[c] - mu * sc;
    }
}

// ---------------- fused: mask_atten = softmax_t(me); out = gamma*pm*mask_atten + BN(wz) ----------------
__global__ void __launch_bounds__(256)
softmax_final(const float* __restrict__ me, const __half* __restrict__ pm,
              const float* __restrict__ wz, const float* __restrict__ scale,
              const float* __restrict__ shift, const float* __restrict__ gamma,
              float* __restrict__ out)
{
    const int blk = blockIdx.x;
    const int c = blk % CC;
    const long long base = (long long)blk * THW;
    const float* p = me + base;
    const int tid = threadIdx.x;
    __shared__ float red[8];

    float v[25];
    float mx = -3.0e38f;
#pragma unroll
    for (int i = 0; i < 25; i++) {
        int idx = tid + (i << 8);
        v[i] = (idx < THW) ? p[idx] : -3.0e38f;
        mx = fmaxf(mx, v[i]);
    }
#pragma unroll
    for (int o = 16; o; o >>= 1) mx = fmaxf(mx, __shfl_xor_sync(0xffffffffu, mx, o));
    if ((tid & 31) == 0) red[tid >> 5] = mx;
    __syncthreads();
    mx = red[0];
#pragma unroll
    for (int w = 1; w < 8; w++) mx = fmaxf(mx, red[w]);
    __syncthreads();

    float s = 0.f;
#pragma unroll
    for (int i = 0; i < 25; i++) { v[i] = __expf(v[i] - mx); s += v[i]; }
#pragma unroll
    for (int o = 16; o; o >>= 1) s += __shfl_xor_sync(0xffffffffu, s, o);
    if ((tid & 31) == 0) red[tid >> 5] = s;
    __syncthreads();
    s = 0.f;
#pragma unroll
    for (int w = 0; w < 8; w++) s += red[w];

    const float inv = 1.f / s;
    const float g  = gamma[0];
    const float sc = scale[c], sh = shift[c];
#pragma unroll
    for (int i = 0; i < 25; i++) {
        int idx = tid + (i << 8);
        if (idx < THW) {
            float ma  = v[i] * inv;
            float pmv = __half2float(pm[base + idx]);
            out[base + idx] = g * pmv * ma + fmaf(wz[base + idx], sc, sh);
        }
    }
}

// ---------------- launch ----------------
extern "C" void kernel_launch(void* const* d_in, const int* in_sizes, int n_in,
                              void* d_out, int out_size)
{
    const float* x    = (const float*)d_in[0];
    const float* mask = (const float*)d_in[1];
    const float* Wh   = (const float*)d_in[2];
    const float* bh   = (const float*)d_in[3];
    const float* Wg   = (const float*)d_in[4];
    const float* bg   = (const float*)d_in[5];
    const float* Wm   = (const float*)d_in[6];
    const float* bm   = (const float*)d_in[7];
    const float* Wz   = (const float*)d_in[8];
    const float* bz   = (const float*)d_in[9];
    const float* bn_w = (const float*)d_in[10];
    const float* bn_b = (const float*)d_in[11];
    const float* gamma= (const float*)d_in[12];
    float* out = (float*)d_out;

    float *wz, *me, *vb, *beta, *scale, *shift;
    __half *att, *xh, *maskT, *whgm, *wT, *MT, *xM, *phm, *pm;
    cudaGetSymbolAddress((void**)&wz,    g_wz);
    cudaGetSymbolAddress((void**)&me,    g_me);
    cudaGetSymbolAddress((void**)&att,   g_att);
    cudaGetSymbolAddress((void**)&xh,    g_xh);
    cudaGetSymbolAddress((void**)&maskT, g_maskT);
    cudaGetSymbolAddress((void**)&whgm,  g_whgm);
    cudaGetSymbolAddress((void**)&wT,    g_wT);
    cudaGetSymbolAddress((void**)&MT,    g_MT);
    cudaGetSymbolAddress((void**)&xM,    g_xM);
    cudaGetSymbolAddress((void**)&phm,   g_phm);
    cudaGetSymbolAddress((void**)&pm,    g_pm);
    cudaGetSymbolAddress((void**)&vb,    g_vb);
    cudaGetSymbolAddress((void**)&beta,  g_beta);
    cudaGetSymbolAddress((void**)&scale, g_scale);
    cudaGetSymbolAddress((void**)&shift, g_shift);

    const long long EE = (long long)EEL;
    const int SMEM_GEMM = STAGES * 32768;   // 96KB
    cudaFuncSetAttribute(gemm_f16_mma,    cudaFuncAttributeMaxDynamicSharedMemorySize, SMEM_GEMM);
    cudaFuncSetAttribute(gemm_f16_f32acc, cudaFuncAttributeMaxDynamicSharedMemorySize, SMEM_GEMM);

    // streams/events (created once on the first, non-captured call)
    static cudaStream_t s1 = nullptr, s2 = nullptr, s3 = nullptr;
    static cudaEvent_t eFork = nullptr, eX = nullptr, eW = nullptr, eBeta = nullptr,
                       ePhm = nullptr, eSide = nullptr, ePrep = nullptr;
    if (!s1) {
        cudaStreamCreateWithFlags(&s1, cudaStreamNonBlocking);
        cudaStreamCreateWithFlags(&s2, cudaStreamNonBlocking);
        cudaStreamCreateWithFlags(&s3, cudaStreamNonBlocking);
        cudaEventCreateWithFlags(&eFork, cudaEventDisableTiming);
        cudaEventCreateWithFlags(&eX,    cudaEventDisableTiming);
        cudaEventCreateWithFlags(&eW,    cudaEventDisableTiming);
        cudaEventCreateWithFlags(&eBeta, cudaEventDisableTiming);
        cudaEventCreateWithFlags(&ePhm,  cudaEventDisableTiming);
        cudaEventCreateWithFlags(&eSide, cudaEventDisableTiming);
        cudaEventCreateWithFlags(&ePrep, cudaEventDisableTiming);
    }

    const dim3 t32(32, 8);

    // ---- fork FIRST so all side streams join the capture graph ----
    cudaEventRecord(eFork, 0);
    cudaStreamWaitEvent(s1, eFork, 0);
    cudaStreamWaitEvent(s2, eFork, 0);
    cudaStreamWaitEvent(s3, eFork, 0);

    // ---- main: critical x transform (fp16 only now) ----
    transpose_cvt<<<dim3(THW / 32, CC / 32, NB), t32>>>(x, xh, CT, CT);
    cudaEventRecord(eX, 0);

    // ---- s1: weight prep -> MT; then beta (needs xh) ----
    vb_k<<<(CC * 32 + 255) / 256, 256, 0, s1>>>(Wg, bh, vb);
    prep_weights<<<(4 * CC * CC + 255) / 256, 256, 0, s1>>>(Wh, Wg, Wm, Wz, whgm, wT);
    cudaEventRecord(ePrep, s1);
    // MT[a,b] = sum_j WgT[a,j]*WhT[b,j] = (Wh^T Wg)^T
    gemm_f16_mma<<<dim3(4, 4, 1), 256, SMEM_GEMM, s1>>>(
        wT + CC * CC, wT, MT, 1, nullptr, nullptr, CC, CC, CC, CC, CC, 0, 0, 0, 0);
    cudaEventRecord(eW, s1);
    cudaStreamWaitEvent(s1, eX, 0);
    beta_k<<<(NB * THW * 32 + 255) / 256, 256, 0, s1>>>(xh, vb, beta);
    cudaEventRecord(eBeta, s1);

    // ---- s2: mask transform -> phm ----
    transpose_cvt<<<dim3(THW / 32, CC / 32, NB), t32, 0, s2>>>(mask, maskT, CT, CT);
    cudaStreamWaitEvent(s2, ePrep, 0);
    gemm_f16_mma<<<dim3(THW / 128, CC / 128, NB), 256, SMEM_GEMM, s2>>>(
        whgm, maskT, phm, 1, bh, nullptr, CC, THW, CC, CC, CC, 0, CT, CT, 0);
    cudaEventRecord(ePhm, s2);

    // ---- s3: pm, wz (fp16 in, fp32 acc), bn_stats ----
    cudaStreamWaitEvent(s3, eX, 0);
    cudaStreamWaitEvent(s3, ePrep, 0);
    gemm_f16_mma<<<dim3(THW / 128, CC / 128, NB), 256, SMEM_GEMM, s3>>>(
        whgm + 2 * CC * CC, xh, pm, 1, bm, nullptr, CC, THW, CC, CC, CC, 0, CT, CT, 0);
    gemm_f16_f32acc<<<dim3(THW / 128, CC / 128, NB), 256, SMEM_GEMM, s3>>>(
        whgm + 3 * CC * CC, xh, wz, bz, CC, THW, CC, CC, CC, 0, CT, CT);
    bn_stats<<<CC, 256, 0, s3>>>(wz, bn_w, bn_b, scale, shift);
    cudaEventRecord(eSide, s3);

    // ---- main chain ----
    cudaStreamWaitEvent(0, eW, 0);
    // xM[t,k] = sum_c xh[t,c]*MT[k,c]
    gemm_f16_mma<<<dim3(CC / 128, THW / 128, NB), 256, SMEM_GEMM>>>(
        xh, MT, xM, 1, nullptr, nullptr, THW, CC, CC, CC, CC, CT, 0, CT, 0);

    cudaStreamWaitEvent(0, eBeta, 0);
    // energy[t,s] = sum_k xM[t,k]*xh[s,k] + beta[s]
    gemm_f16_mma<<<dim3(THW / 128, THW / 128, NB), 256, SMEM_GEMM>>>(
        xM, xh, att, 1, nullptr, beta, THW, THW, CC, CC, CC, CT, CT, EE, THW);

    softmax_h<<<NB * THW, 256>>>(att, THW);

    cudaStreamWaitEvent(0, ePhm, 0);
    // mask_energy[c,t] = sum_s phm[c,s]*att[t,s]
    gemm_f16_mma<<<dim3(THW / 128, CC / 128, NB), 256, SMEM_GEMM>>>(
        phm, att, me, 0, nullptr, nullptr, CC, THW, THW, THW, THW, CT, EE, CT, 0);

    cudaStreamWaitEvent(0, eSide, 0);
    softmax_final<<<NB * CC, 256>>>(me, pm, wz, scale, shift, gamma, out);
}

// round 17
// speedup vs baseline: 1.1462x; 1.0482x over previous
#include <cuda_runtime.h>
#include <cuda_fp16.h>
#include <cstdint>

#define NB  2
#define CC  512
#define THW 6272
#define CT  (CC*THW)
#define EEL ((size_t)THW*(size_t)THW)

// ---------------- device scratch ----------------
__device__ float g_wz[NB*CT];                        // fp32 Wz projection [c,t]
__device__ float g_me[NB*CT];                        // mask_energy fp32
__device__ __half g_att [NB*EEL];                    // energy -> attention fp16 [t,s]
__device__ __half g_xh  [NB*CT];                     // x^T [t,c] fp16
__device__ __half g_maskT[NB*CT];                    // mask^T [s,c] fp16
__device__ __half g_whgm[4*CC*CC];                   // Wh,Wg,Wm,Wz fp16 [o,c]
__device__ __half g_wT  [2*CC*CC];                   // WhT,WgT fp16 [c,o]
__device__ __half g_MT  [CC*CC];                     // (Wh^T Wg)^T fp16 [k,c]
__device__ __half g_xM  [NB*CT];                     // x^T(Wh^T Wg) fp16 [t,k]
__device__ __half g_phm [NB*CT];                     // [c,s] fp16
__device__ __half g_pm  [NB*CT];                     // [c,t] fp16
__device__ float g_vb  [CC];                         // Wg^T bh
__device__ float g_beta[NB*THW];                     // x^T (Wg^T bh)  [s]
__device__ float g_scale[CC];
__device__ float g_shift[CC];

// ---------------- helpers ----------------
__device__ __forceinline__ uint32_t smem_u32(const void* p) {
    uint32_t a;
    asm("{ .reg .u64 t; cvta.to.shared.u64 t, %1; cvt.u32.u64 %0, t; }" : "=r"(a) : "l"(p));
    return a;
}
#define SWZ128(o) ((o) ^ (((o) >> 3) & 0x70))
__device__ __forceinline__ void cp16(uint32_t s, const void* g) {
    asm volatile("cp.async.cg.shared.global [%0], [%1], 16;" :: "r"(s), "l"(g));
}
#define CP_COMMIT() asm volatile("cp.async.commit_group;" ::: "memory")
#define CP_WAIT(n)  asm volatile("cp.async.wait_group %0;" :: "n"(n) : "memory")

__device__ __forceinline__ void ldmx4(uint32_t& r0, uint32_t& r1, uint32_t& r2, uint32_t& r3,
                                      uint32_t addr) {
    asm volatile("ldmatrix.sync.aligned.m8n8.x4.shared.b16 {%0,%1,%2,%3}, [%4];"
                 : "=r"(r0), "=r"(r1), "=r"(r2), "=r"(r3) : "r"(addr));
}
__device__ __forceinline__ void mma_f16f32(float* d, const uint32_t* a, const uint32_t* b) {
    asm volatile("mma.sync.aligned.m16n8k16.row.col.f32.f16.f16.f32 "
                 "{%0,%1,%2,%3}, {%4,%5,%6,%7}, {%8,%9}, {%0,%1,%2,%3};"
                 : "+f"(d[0]), "+f"(d[1]), "+f"(d[2]), "+f"(d[3])
                 : "r"(a[0]), "r"(a[1]), "r"(a[2]), "r"(a[3]), "r"(b[0]), "r"(b[1]));
}
__device__ __forceinline__ void mma_f16(uint32_t* d, const uint32_t* a, const uint32_t* b) {
    asm volatile("mma.sync.aligned.m16n8k16.row.col.f16.f16.f16.f16 "
                 "{%0,%1}, {%2,%3,%4,%5}, {%6,%7}, {%0,%1};"
                 : "+r"(d[0]), "+r"(d[1])
                 : "r"(a[0]), "r"(a[1]), "r"(a[2]), "r"(a[3]), "r"(b[0]), "r"(b[1]));
}

#define STAGES 3

// ================= fp16 HMMA TN GEMM (fp16 accumulate) =================
// C[m,n] = sum_k A[m,k]*B[n,k] (+bias_m[m]) (+bias_n[z*sBiasN + n]); out_kind: 0=f32, 1=f16
__global__ void __launch_bounds__(256)
gemm_f16_mma(const __half* __restrict__ A, const __half* __restrict__ B,
             void* __restrict__ Cv, int out_kind,
             const float* __restrict__ bias_m, const float* __restrict__ bias_n,
             int M, int N, int K, int ldA, int ldB,
             long long sA, long long sB, long long sC, long long sBiasN)
{
    extern __shared__ char smem[];
    const uint32_t sb = smem_u32(smem);
    const int tid = threadIdx.x, wid = tid >> 5, lane = tid & 31;
    const int wm = wid & 1, wn = wid >> 1;
    const int m_w = wm * 64, n_w = wn * 32;

    uint32_t bufA[STAGES], bufB[STAGES];
#pragma unroll
    for (int s = 0; s < STAGES; s++) { bufA[s] = sb + s * 32768; bufB[s] = bufA[s] + 16384; }

    const int m0 = blockIdx.y * 128, n0 = blockIdx.x * 128;
    const char* Ab = (const char*)(A + (long long)blockIdx.z * sA + (long long)m0 * ldA);
    const char* Bb = (const char*)(B + (long long)blockIdx.z * sB + (long long)n0 * ldB);
    const long long rbA = (long long)ldA * 2;
    const long long rbB = (long long)ldB * 2;
    const int nc = K >> 6;

    const int lrow = tid >> 3;
    const int lcol = (tid & 7) << 4;

    auto load_chunk = [&](int c, int s) {
        const char* ga = Ab + (long long)c * 128;
        const char* gb = Bb + (long long)c * 128;
#pragma unroll
        for (int i = 0; i < 4; i++) {
            int row = lrow + i * 32;
            uint32_t off = SWZ128((uint32_t)(row * 128 + lcol));
            long long go = (long long)row;
            cp16(bufA[s] + off, ga + go * rbA + lcol);
            cp16(bufB[s] + off, gb + go * rbB + lcol);
        }
    };

    uint32_t acc[4][4][2];
#pragma unroll
    for (int i = 0; i < 4; i++)
#pragma unroll
        for (int j = 0; j < 4; j++) { acc[i][j][0] = 0u; acc[i][j][1] = 0u; }

    const int grp = lane >> 3, rw = lane & 7;
    const int a_row = (grp & 1) * 8 + rw;
    const int a_kh  = (grp >> 1) * 16;
    const int b_row = (grp >> 1) * 8 + rw;
    const int b_kh  = (grp & 1) * 16;

    load_chunk(0, 0); CP_COMMIT();
    if (nc > 1) { load_chunk(1, 1); CP_COMMIT(); }

    for (int c = 0; c < nc; c++) {
        if (c + 1 < nc) { CP_WAIT(1); } else { CP_WAIT(0); }
        __syncthreads();
        if (c + 2 < nc) { load_chunk(c + 2, (c + 2) % STAGES); CP_COMMIT(); }
        const uint32_t sa = bufA[c % STAGES], sbm = bufB[c % STAGES];
#pragma unroll
        for (int kk = 0; kk < 4; kk++) {
            const int kb = kk * 32;
            uint32_t a[4][4], b[4][2];
#pragma unroll
            for (int mt = 0; mt < 4; mt++) {
                int row = m_w + mt * 16 + a_row;
                uint32_t ad = sa + SWZ128((uint32_t)(row * 128 + kb + a_kh));
                ldmx4(a[mt][0], a[mt][1], a[mt][2], a[mt][3], ad);
            }
#pragma unroll
            for (int np = 0; np < 2; np++) {
                int row = n_w + np * 16 + b_row;
                uint32_t bd = sbm + SWZ128((uint32_t)(row * 128 + kb + b_kh));
                uint32_t r0, r1, r2, r3;
                ldmx4(r0, r1, r2, r3, bd);
                b[np * 2][0] = r0; b[np * 2][1] = r1;
                b[np * 2 + 1][0] = r2; b[np * 2 + 1][1] = r3;
            }
#pragma unroll
            for (int mt = 0; mt < 4; mt++)
#pragma unroll
                for (int nt = 0; nt < 4; nt++)
                    mma_f16(acc[mt][nt], a[mt], b[nt]);
        }
    }

    const int r_lo = lane >> 2, c_off = (lane & 3) * 2;
    const float* bnz = bias_n ? (bias_n + (long long)blockIdx.z * sBiasN) : nullptr;
#pragma unroll
    for (int mt = 0; mt < 4; mt++) {
        int row = m0 + m_w + mt * 16 + r_lo;
#pragma unroll
        for (int half = 0; half < 2; half++) {
            int r = row + half * 8;
            float bmv = bias_m ? bias_m[r] : 0.f;
            long long base = (long long)blockIdx.z * sC + (long long)r * N + n0 + n_w + c_off;
#pragma unroll
            for (int nt = 0; nt < 4; nt++) {
                float2 v = __half22float2(*reinterpret_cast<__half2*>(&acc[mt][nt][half]));
                v.x += bmv; v.y += bmv;
                int col = n0 + n_w + nt * 8 + c_off;
                if (bnz) { v.x += bnz[col]; v.y += bnz[col + 1]; }
                if (out_kind == 1) {
                    *reinterpret_cast<__half2*>((__half*)Cv + base + nt * 8) =
                        __floats2half2_rn(v.x, v.y);
                } else {
                    *reinterpret_cast<float2*>((float*)Cv + base + nt * 8) = v;
                }
            }
        }
    }
}

// ================= fp16 HMMA TN GEMM with fp32 accumulate (wz branch) =================
__global__ void __launch_bounds__(256)
gemm_f16_f32acc(const __half* __restrict__ A, const __half* __restrict__ B,
                float* __restrict__ Cv, const float* __restrict__ bias_m,
                int M, int N, int K, int ldA, int ldB,
                long long sA, long long sB, long long sC)
{
    extern __shared__ char smem[];
    const uint32_t sb = smem_u32(smem);
    const int tid = threadIdx.x, wid = tid >> 5, lane = tid & 31;
    const int wm = wid & 1, wn = wid >> 1;
    const int m_w = wm * 64, n_w = wn * 32;

    uint32_t bufA[STAGES], bufB[STAGES];
#pragma unroll
    for (int s = 0; s < STAGES; s++) { bufA[s] = sb + s * 32768; bufB[s] = bufA[s] + 16384; }

    const int m0 = blockIdx.y * 128, n0 = blockIdx.x * 128;
    const char* Ab = (const char*)(A + (long long)blockIdx.z * sA + (long long)m0 * ldA);
    const char* Bb = (const char*)(B + (long long)blockIdx.z * sB + (long long)n0 * ldB);
    const long long rbA = (long long)ldA * 2;
    const long long rbB = (long long)ldB * 2;
    const int nc = K >> 6;

    const int lrow = tid >> 3;
    const int lcol = (tid & 7) << 4;

    auto load_chunk = [&](int c, int s) {
        const char* ga = Ab + (long long)c * 128;
        const char* gb = Bb + (long long)c * 128;
#pragma unroll
        for (int i = 0; i < 4; i++) {
            int row = lrow + i * 32;
            uint32_t off = SWZ128((uint32_t)(row * 128 + lcol));
            long long go = (long long)row;
            cp16(bufA[s] + off, ga + go * rbA + lcol);
            cp16(bufB[s] + off, gb + go * rbB + lcol);
        }
    };

    float acc[4][4][4];
#pragma unroll
    for (int i = 0; i < 4; i++)
#pragma unroll
        for (int j = 0; j < 4; j++)
#pragma unroll
            for (int q = 0; q < 4; q++) acc[i][j][q] = 0.f;

    const int grp = lane >> 3, rw = lane & 7;
    const int a_row = (grp & 1) * 8 + rw;
    const int a_kh  = (grp >> 1) * 16;
    const int b_row = (grp >> 1) * 8 + rw;
    const int b_kh  = (grp & 1) * 16;

    load_chunk(0, 0); CP_COMMIT();
    if (nc > 1) { load_chunk(1, 1); CP_COMMIT(); }

    for (int c = 0; c < nc; c++) {
        if (c + 1 < nc) { CP_WAIT(1); } else { CP_WAIT(0); }
        __syncthreads();
        if (c + 2 < nc) { load_chunk(c + 2, (c + 2) % STAGES); CP_COMMIT(); }
        const uint32_t sa = bufA[c % STAGES], sbm = bufB[c % STAGES];
#pragma unroll
        for (int kk = 0; kk < 4; kk++) {
            const int kb = kk * 32;
            uint32_t a[4][4], b[4][2];
#pragma unroll
            for (int mt = 0; mt < 4; mt++) {
                int row = m_w + mt * 16 + a_row;
                uint32_t ad = sa + SWZ128((uint32_t)(row * 128 + kb + a_kh));
                ldmx4(a[mt][0], a[mt][1], a[mt][2], a[mt][3], ad);
            }
#pragma unroll
            for (int np = 0; np < 2; np++) {
                int row = n_w + np * 16 + b_row;
                uint32_t bd = sbm + SWZ128((uint32_t)(row * 128 + kb + b_kh));
                uint32_t r0, r1, r2, r3;
                ldmx4(r0, r1, r2, r3, bd);
                b[np * 2][0] = r0; b[np * 2][1] = r1;
                b[np * 2 + 1][0] = r2; b[np * 2 + 1][1] = r3;
            }
#pragma unroll
            for (int mt = 0; mt < 4; mt++)
#pragma unroll
                for (int nt = 0; nt < 4; nt++)
                    mma_f16f32(acc[mt][nt], a[mt], b[nt]);
        }
    }

    const int r_lo = lane >> 2, c_off = (lane & 3) * 2;
#pragma unroll
    for (int mt = 0; mt < 4; mt++) {
        int row = m0 + m_w + mt * 16 + r_lo;
#pragma unroll
        for (int half = 0; half < 2; half++) {
            int r = row + half * 8;
            float bmv = bias_m ? bias_m[r] : 0.f;
            long long base = (long long)blockIdx.z * sC + (long long)r * N + n0 + n_w + c_off;
#pragma unroll
            for (int nt = 0; nt < 4; nt++) {
                float v0 = acc[mt][nt][half * 2 + 0] + bmv;
                float v1 = acc[mt][nt][half * 2 + 1] + bmv;
                *reinterpret_cast<float2*>(Cv + base + nt * 8) = make_float2(v0, v1);
            }
        }
    }
}

// ---------------- prep: Wh,Wg,Wm,Wz -> fp16 [o,c]; WhT,WgT fp16 [c,o] ----------------
__global__ void prep_weights(const float* __restrict__ Wh, const float* __restrict__ Wg,
                             const float* __restrict__ Wm, const float* __restrict__ Wz,
                             __half* __restrict__ whgm, __half* __restrict__ wT)
{
    int i = blockIdx.x * blockDim.x + threadIdx.x;
    int n = CC * CC;
    if (i < n) {
        int o = i / CC, c = i - o * CC;
        __half h = __float2half(Wh[i]);
        whgm[i] = h;
        wT[c * CC + o] = h;                    // WhT
    } else if (i < 2 * n) {
        int j = i - n;
        int o = j / CC, c = j - o * CC;
        __half h = __float2half(Wg[j]);
        whgm[i] = h;
        wT[n + c * CC + o] = h;                // WgT
    } else if (i < 3 * n) {
        whgm[i] = __float2half(Wm[i - 2 * n]);
    } else if (i < 4 * n) {
        whgm[i] = __float2half(Wz[i - 3 * n]);
    }
}

// ---------------- vb[c] = sum_o Wg[o,c]*bh[o]  (one warp per c) ----------------
__global__ void __launch_bounds__(256)
vb_k(const float* __restrict__ Wg, const float* __restrict__ bh, float* __restrict__ vb)
{
    int c = (blockIdx.x * blockDim.x + threadIdx.x) >> 5;
    int lane = threadIdx.x & 31;
    if (c >= CC) return;
    float s = 0.f;
#pragma unroll
    for (int i = 0; i < 16; i++) {
        int o = lane + i * 32;
        s += Wg[o * CC + c] * bh[o];
    }
#pragma unroll
    for (int o = 16; o; o >>= 1) s += __shfl_xor_sync(0xffffffffu, s, o);
    if (lane == 0) vb[c] = s;
}

// ---------------- transpose + fp32->fp16 ([c,t] -> [t,c]) ----------------
__global__ void transpose_cvt(const float* __restrict__ in, __half* __restrict__ out,
                              long long sIn, long long sOut)
{
    __shared__ float tile[32][33];
    const float* ib = in + (long long)blockIdx.z * sIn;
    __half* ob = out + (long long)blockIdx.z * sOut;
    int t0 = blockIdx.x * 32, c0 = blockIdx.y * 32;
    int x = threadIdx.x, y = threadIdx.y;
#pragma unroll
    for (int i = 0; i < 32; i += 8)
        tile[y + i][x] = ib[(long long)(c0 + y + i) * THW + t0 + x];
    __syncthreads();
#pragma unroll
    for (int i = 0; i < 32; i += 8)
        ob[(long long)(t0 + y + i) * CC + c0 + x] = __float2half(tile[x][y + i]);
}

// ---------------- beta[z][s] = sum_c xh[z][s,c] * vb[c]  (one warp per row) ----------------
__global__ void __launch_bounds__(256)
beta_k(const __half* __restrict__ xh, const float* __restrict__ vb,
       float* __restrict__ beta)
{
    int wrow = (blockIdx.x * blockDim.x + threadIdx.x) >> 5;
    int lane = threadIdx.x & 31;
    if (wrow >= NB * THW) return;
    const __half* p = xh + (long long)wrow * CC;
    float s = 0.f;
#pragma unroll
    for (int i = 0; i < 16; i++) {
        int c = lane + i * 32;
        s += __half2float(p[c]) * vb[c];
    }
#pragma unroll
    for (int o = 16; o; o >>= 1) s += __shfl_xor_sync(0xffffffffu, s, o);
    if (lane == 0) beta[wrow] = s;
}

// ---------------- softmax fp16 in-place, vectorized 16B (rowlen = THW = 784 uint4) ----------------
#define V4 784     // THW/8
__global__ void __launch_bounds__(256)
softmax_h(__half* __restrict__ data)
{
    uint4* p = reinterpret_cast<uint4*>(data + (long long)blockIdx.x * THW);
    const int tid = threadIdx.x;
    __shared__ float red[8];

    uint4 raw[4];
    float v[4][8];
    float mx = -3.0e38f;
#pragma unroll
    for (int k = 0; k < 4; k++) {
        int idx = tid + (k << 8);
        if (idx < V4) {
            raw[k] = p[idx];
            const __half2* h2 = reinterpret_cast<const __half2*>(&raw[k]);
#pragma unroll
            for (int j = 0; j < 4; j++) {
                float2 f = __half22float2(h2[j]);
                v[k][j * 2]     = f.x;
                v[k][j * 2 + 1] = f.y;
                mx = fmaxf(mx, fmaxf(f.x, f.y));
            }
        } else {
#pragma unroll
            for (int j = 0; j < 8; j++) v[k][j] = -3.0e38f;
        }
    }
#pragma unroll
    for (int o = 16; o; o >>= 1) mx = fmaxf(mx, __shfl_xor_sync(0xffffffffu, mx, o));
    if ((tid & 31) == 0) red[tid >> 5] = mx;
    __syncthreads();
    mx = red[0];
#pragma unroll
    for (int w = 1; w < 8; w++) mx = fmaxf(mx, red[w]);
    __syncthreads();

    float s = 0.f;
#pragma unroll
    for (int k = 0; k < 4; k++)
#pragma unroll
        for (int j = 0; j < 8; j++) { v[k][j] = __expf(v[k][j] - mx); s += v[k][j]; }
#pragma unroll
    for (int o = 16; o; o >>= 1) s += __shfl_xor_sync(0xffffffffu, s, o);
    if ((tid & 31) == 0) red[tid >> 5] = s;
    __syncthreads();
    s = 0.f;
#pragma unroll
    for (int w = 0; w < 8; w++) s += red[w];
    const float inv = 1.f / s;

#pragma unroll
    for (int k = 0; k < 4; k++) {
        int idx = tid + (k << 8);
        if (idx < V4) {
            uint4 o4;
            __half2* h2 = reinterpret_cast<__half2*>(&o4);
#pragma unroll
            for (int j = 0; j < 4; j++)
                h2[j] = __floats2half2_rn(v[k][j * 2] * inv, v[k][j * 2 + 1] * inv);
            p[idx] = o4;
        }
    }
}

// ---------------- BN stats on g_wz ----------------
__global__ void __launch_bounds__(256)
bn_stats(const float* __restrict__ wz, const float* __restrict__ bn_w,
         const float* __restrict__ bn_b, float* __restrict__ scale,
         float* __restrict__ shift)
{
    int c = blockIdx.x;
    int tid = threadIdx.x;
    float s = 0.f, sq = 0.f;
    for (int i = tid; i < NB * THW; i += 256) {
        int n = i / THW, t = i - n * THW;
        float v = wz[(long long)n * CT + (long long)c * THW + t];
        s += v;
        sq = fmaf(v, v, sq);
    }
    __shared__ float r1[8], r2[8];
#pragma unroll
    for (int o = 16; o; o >>= 1) {
        s  += __shfl_xor_sync(0xffffffffu, s,  o);
        sq += __shfl_xor_sync(0xffffffffu, sq, o);
    }
    if ((tid & 31) == 0) { r1[tid >> 5] = s; r2[tid >> 5] = sq; }
    __syncthreads();
    if (tid == 0) {
        s = 0.f; sq = 0.f;
#pragma unroll
        for (int w = 0; w < 8; w++) { s += r1[w]; sq += r2[w]; }
        const float invn = 1.f / (float)(NB * THW);
        float mu  = s * invn;
        float var = sq * invn - mu * mu;
        float sc  = bn_w[c] * rsqrtf(var + 1e-5f);
        scale[c] = sc;
        shift[c] = bn_b[c] - mu * sc;
    }
}

// ---------------- fused softmax_t(me) + final combine, vectorized float4 ----------------
#define VF4 1568   // THW/4
__global__ void __launch_bounds__(256)
softmax_final(const float* __restrict__ me, const __half* __restrict__ pm,
              const float* __restrict__ wz, const float* __restrict__ scale,
              const float* __restrict__ shift, const float* __restrict__ gamma,
              float* __restrict__ out)
{
    const int blk = blockIdx.x;
    const int c = blk % CC;
    const long long base = (long long)blk * THW;
    const float4* p = reinterpret_cast<const float4*>(me + base);
    const int tid = threadIdx.x;
    __shared__ float red[8];

    float v[7][4];
    float mx = -3.0e38f;
#pragma unroll
    for (int k = 0; k < 7; k++) {
        int idx = tid + (k << 8);
        if (idx < VF4) {
            float4 f = p[idx];
            v[k][0] = f.x; v[k][1] = f.y; v[k][2] = f.z; v[k][3] = f.w;
            mx = fmaxf(mx, fmaxf(fmaxf(f.x, f.y), fmaxf(f.z, f.w)));
        } else {
#pragma unroll
            for (int j = 0; j < 4; j++) v[k][j] = -3.0e38f;
        }
    }
#pragma unroll
    for (int o = 16; o; o >>= 1) mx = fmaxf(mx, __shfl_xor_sync(0xffffffffu, mx, o));
    if ((tid & 31) == 0) red[tid >> 5] = mx;
    __syncthreads();
    mx = red[0];
#pragma unroll
    for (int w = 1; w < 8; w++) mx = fmaxf(mx, red[w]);
    __syncthreads();

    float s = 0.f;
#pragma unroll
    for (int k = 0; k < 7; k++)
#pragma unroll
        for (int j = 0; j < 4; j++) { v[k][j] = __expf(v[k][j] - mx); s += v[k][j]; }
#pragma unroll
    for (int o = 16; o; o >>= 1) s += __shfl_xor_sync(0xffffffffu, s, o);
    if ((tid & 31) == 0) red[tid >> 5] = s;
    __syncthreads();
    s = 0.f;
#pragma unroll
    for (int w = 0; w < 8; w++) s += red[w];

    const float inv = 1.f / s;
    const float g  = gamma[0];
    const float sc = scale[c], sh = shift[c];
    const float4* wz4 = reinterpret_cast<const float4*>(wz + base);
    const uint2*  pm4 = reinterpret_cast<const uint2*>(pm + base);   // 4 halfs
    float4* out4 = reinterpret_cast<float4*>(out + base);
#pragma unroll
    for (int k = 0; k < 7; k++) {
        int idx = tid + (k << 8);
        if (idx < VF4) {
            float4 w4 = wz4[idx];
            uint2 pmraw = pm4[idx];
            const __half2* ph = reinterpret_cast<const __half2*>(&pmraw);
            float2 p0 = __half22float2(ph[0]);
            float2 p1 = __half22float2(ph[1]);
            float4 o4;
            o4.x = g * p0.x * (v[k][0] * inv) + fmaf(w4.x, sc, sh);
            o4.y = g * p0.y * (v[k][1] * inv) + fmaf(w4.y, sc, sh);
            o4.z = g * p1.x * (v[k][2] * inv) + fmaf(w4.z, sc, sh);
            o4.w = g * p1.y * (v[k][3] * inv) + fmaf(w4.w, sc, sh);
            out4[idx] = o4;
        }
    }
}

// ---------------- launch ----------------
extern "C" void kernel_launch(void* const* d_in, const int* in_sizes, int n_in,
                              void* d_out, int out_size)
{
    const float* x    = (const float*)d_in[0];
    const float* mask = (const float*)d_in[1];
    const float* Wh   = (const float*)d_in[2];
    const float* bh   = (const float*)d_in[3];
    const float* Wg   = (const float*)d_in[4];
    const float* bg   = (const float*)d_in[5];
    const float* Wm   = (const float*)d_in[6];
    const float* bm   = (const float*)d_in[7];
    const float* Wz   = (const float*)d_in[8];
    const float* bz   = (const float*)d_in[9];
    const float* bn_w = (const float*)d_in[10];
    const float* bn_b = (const float*)d_in[11];
    const float* gamma= (const float*)d_in[12];
    float* out = (float*)d_out;

    float *wz, *me, *vb, *beta, *scale, *shift;
    __half *att, *xh, *maskT, *whgm, *wT, *MT, *xM, *phm, *pm;
    cudaGetSymbolAddress((void**)&wz,    g_wz);
    cudaGetSymbolAddress((void**)&me,    g_me);
    cudaGetSymbolAddress((void**)&att,   g_att);
    cudaGetSymbolAddress((void**)&xh,    g_xh);
    cudaGetSymbolAddress((void**)&maskT, g_maskT);
    cudaGetSymbolAddress((void**)&whgm,  g_whgm);
    cudaGetSymbolAddress((void**)&wT,    g_wT);
    cudaGetSymbolAddress((void**)&MT,    g_MT);
    cudaGetSymbolAddress((void**)&xM,    g_xM);
    cudaGetSymbolAddress((void**)&phm,   g_phm);
    cudaGetSymbolAddress((void**)&pm,    g_pm);
    cudaGetSymbolAddress((void**)&vb,    g_vb);
    cudaGetSymbolAddress((void**)&beta,  g_beta);
    cudaGetSymbolAddress((void**)&scale, g_scale);
    cudaGetSymbolAddress((void**)&shift, g_shift);

    const long long EE = (long long)EEL;
    const int SMEM_GEMM = STAGES * 32768;   // 96KB
    cudaFuncSetAttribute(gemm_f16_mma,    cudaFuncAttributeMaxDynamicSharedMemorySize, SMEM_GEMM);
    cudaFuncSetAttribute(gemm_f16_f32acc, cudaFuncAttributeMaxDynamicSharedMemorySize, SMEM_GEMM);

    // streams/events (created once on the first, non-captured call)
    static cudaStream_t s1 = nullptr, s2 = nullptr, s3 = nullptr;
    static cudaEvent_t eFork = nullptr, eX = nullptr, eW = nullptr, eBeta = nullptr,
                       ePhm = nullptr, eSide = nullptr, ePrep = nullptr;
    if (!s1) {
        cudaStreamCreateWithFlags(&s1, cudaStreamNonBlocking);
        cudaStreamCreateWithFlags(&s2, cudaStreamNonBlocking);
        cudaStreamCreateWithFlags(&s3, cudaStreamNonBlocking);
        cudaEventCreateWithFlags(&eFork, cudaEventDisableTiming);
        cudaEventCreateWithFlags(&eX,    cudaEventDisableTiming);
        cudaEventCreateWithFlags(&eW,    cudaEventDisableTiming);
        cudaEventCreateWithFlags(&eBeta, cudaEventDisableTiming);
        cudaEventCreateWithFlags(&ePhm,  cudaEventDisableTiming);
        cudaEventCreateWithFlags(&eSide, cudaEventDisableTiming);
        cudaEventCreateWithFlags(&ePrep, cudaEventDisableTiming);
    }

    const dim3 t32(32, 8);

    // ---- fork FIRST so all side streams join the capture graph ----
    cudaEventRecord(eFork, 0);
    cudaStreamWaitEvent(s1, eFork, 0);
    cudaStreamWaitEvent(s2, eFork, 0);
    cudaStreamWaitEvent(s3, eFork, 0);

    // ---- main: critical x transform ----
    transpose_cvt<<<dim3(THW / 32, CC / 32, NB), t32>>>(x, xh, CT, CT);
    cudaEventRecord(eX, 0);

    // ---- s1: weight prep -> MT; then beta (needs xh) ----
    vb_k<<<(CC * 32 + 255) / 256, 256, 0, s1>>>(Wg, bh, vb);
    prep_weights<<<(4 * CC * CC + 255) / 256, 256, 0, s1>>>(Wh, Wg, Wm, Wz, whgm, wT);
    cudaEventRecord(ePrep, s1);
    gemm_f16_mma<<<dim3(4, 4, 1), 256, SMEM_GEMM, s1>>>(
        wT + CC * CC, wT, MT, 1, nullptr, nullptr, CC, CC, CC, CC, CC, 0, 0, 0, 0);
    cudaEventRecord(eW, s1);
    cudaStreamWaitEvent(s1, eX, 0);
    beta_k<<<(NB * THW * 32 + 255) / 256, 256, 0, s1>>>(xh, vb, beta);
    cudaEventRecord(eBeta, s1);

    // ---- s2: mask transform -> phm ----
    transpose_cvt<<<dim3(THW / 32, CC / 32, NB), t32, 0, s2>>>(mask, maskT, CT, CT);
    cudaStreamWaitEvent(s2, ePrep, 0);
    gemm_f16_mma<<<dim3(THW / 128, CC / 128, NB), 256, SMEM_GEMM, s2>>>(
        whgm, maskT, phm, 1, bh, nullptr, CC, THW, CC, CC, CC, 0, CT, CT, 0);
    cudaEventRecord(ePhm, s2);

    // ---- s3: pm, wz, bn_stats ----
    cudaStreamWaitEvent(s3, eX, 0);
    cudaStreamWaitEvent(s3, ePrep, 0);
    gemm_f16_mma<<<dim3(THW / 128, CC / 128, NB), 256, SMEM_GEMM, s3>>>(
        whgm + 2 * CC * CC, xh, pm, 1, bm, nullptr, CC, THW, CC, CC, CC, 0, CT, CT, 0);
    gemm_f16_f32acc<<<dim3(THW / 128, CC / 128, NB), 256, SMEM_GEMM, s3>>>(
        whgm + 3 * CC * CC, xh, wz, bz, CC, THW, CC, CC, CC, 0, CT, CT);
    bn_stats<<<CC, 256, 0, s3>>>(wz, bn_w, bn_b, scale, shift);
    cudaEventRecord(eSide, s3);

    // ---- main chain ----
    cudaStreamWaitEvent(0, eW, 0);
    gemm_f16_mma<<<dim3(CC / 128, THW / 128, NB), 256, SMEM_GEMM>>>(
        xh, MT, xM, 1, nullptr, nullptr, THW, CC, CC, CC, CC, CT, 0, CT, 0);

    cudaStreamWaitEvent(0, eBeta, 0);
    gemm_f16_mma<<<dim3(THW / 128, THW / 128, NB), 256, SMEM_GEMM>>>(
        xM, xh, att, 1, nullptr, beta, THW, THW, CC, CC, CC, CT, CT, EE, THW);

    softmax_h<<<NB * THW, 256>>>(att);

    cudaStreamWaitEvent(0, ePhm, 0);
    gemm_f16_mma<<<dim3(THW / 128, CC / 128, NB), 256, SMEM_GEMM>>>(
        phm, att, me, 0, nullptr, nullptr, CC, THW, THW, THW, THW, CT, EE, CT, 0);

    cudaStreamWaitEvent(0, eSide, 0);
    softmax_final<<<NB * CC, 256>>>(me, pm, wz, scale, shift, gamma, out);
}